// round 2
// baseline (speedup 1.0000x reference)
#include <cuda_runtime.h>
#include <math.h>

#define NN 50000
#define NE 800000
#define NE2 850000   /* NE + NN self loops */

// ---------------- device scratch (alloc-free rule: __device__ globals) ----------------
__device__ __align__(16) float    g_x1[(size_t)NN * 256];
__device__ __align__(16) float    g_x2[(size_t)NN * 128];
__device__ __align__(16) float    g_A [(size_t)NN * 256];
__device__ __align__(16) float    g_B [(size_t)NN * 256];
__device__ __align__(16) float    g_C [(size_t)NN * 256];
__device__ __align__(16) float    g_D [(size_t)NN * 128];
__device__ __align__(16) float    g_ea[(size_t)NE2 * 4];
__device__ unsigned g_amax[(size_t)NN * 4];
__device__ float    g_asum[(size_t)NN * 4];
__device__ float    g_dinv[NN];
__device__ int      g_src[NE];
__device__ int      g_dst[NE];
__device__ int      g_eflag[1];

static inline int divup(long long a, int b) { return (int)((a + b - 1) / b); }

// ---------------- edge-index dtype detection + conversion ----------------
// If edge_index is int64 (values < 50000), every odd 32-bit word is 0.
// If int32, odd words are random node ids (virtually never all zero).
__global__ void k_detect(const int* __restrict__ ei32) {
    __shared__ int cnt;
    if (threadIdx.x == 0) cnt = 0;
    __syncthreads();
    int nz = 0;
    for (int i = threadIdx.x; i < 2048; i += blockDim.x)
        if (ei32[2 * i + 1] != 0) nz++;
    atomicAdd(&cnt, nz);
    __syncthreads();
    if (threadIdx.x == 0) g_eflag[0] = (cnt == 0) ? 1 : 0;  // 1 = int64
}

__global__ void k_convert(const int* __restrict__ ei32,
                          int* __restrict__ src, int* __restrict__ dst) {
    int e = blockIdx.x * blockDim.x + threadIdx.x;
    if (e >= NE) return;
    int is64 = g_eflag[0];
    int s, d;
    if (is64) { s = ei32[2 * e]; d = ei32[2 * (NE + e)]; }
    else      { s = ei32[e];     d = ei32[NE + e]; }
    s = min(max(s, 0), NN - 1);
    d = min(max(d, 0), NN - 1);
    src[e] = s;
    dst[e] = d;
}

// ---------------- elementwise helpers ----------------
__global__ void k_fill_f(float* p, int n, float v) {
    int i = blockIdx.x * blockDim.x + threadIdx.x;
    if (i < n) p[i] = v;
}
__global__ void k_fill_u(unsigned* p, int n, unsigned v) {
    int i = blockIdx.x * blockDim.x + threadIdx.x;
    if (i < n) p[i] = v;
}
__global__ void k_deg(const int* __restrict__ dst, float* __restrict__ deg) {
    int e = blockIdx.x * blockDim.x + threadIdx.x;
    if (e < NE) atomicAdd(&deg[dst[e]], 1.0f);
}
__global__ void k_rsqrt(float* p, int n) {
    int i = blockIdx.x * blockDim.x + threadIdx.x;
    if (i < n) p[i] = rsqrtf(p[i]);
}
__global__ void k_relu(float* p, int n) {
    int i = blockIdx.x * blockDim.x + threadIdx.x;
    if (i < n) p[i] = fmaxf(p[i], 0.0f);
}
__global__ void k_mix(float* a, const float* __restrict__ b, int n) {
    int i = blockIdx.x * blockDim.x + threadIdx.x;
    if (i < n) a[i] = 0.5f * (a[i] + b[i]);
}
__global__ void k_binit128(float* o, const float* __restrict__ bias) {
    int i = blockIdx.x * blockDim.x + threadIdx.x;
    if (i < NN * 128) o[i] = bias[i & 127];
}

// ---------------- GEMM: C[n,k] = A[n,m] @ W[m,k]  (optional GCN2 epilogue + relu) ----------------
#define BM 64
#define BN 64
#define BK 16
template <bool GCN2>
__global__ void gemm_k(const float* __restrict__ A, const float* __restrict__ W,
                       float* __restrict__ C, int n, int m, int k, float beta) {
    __shared__ float As[BK][BM];
    __shared__ float Ws[BK][BN];
    int tid  = threadIdx.x;
    int row0 = blockIdx.y * BM;
    int col0 = blockIdx.x * BN;
    int ty = tid >> 4, tx = tid & 15;
    float acc[4][4] = {};
    for (int mb = 0; mb < m; mb += BK) {
        #pragma unroll
        for (int i = 0; i < 4; i++) {
            int idx = tid + i * 256;
            int r = idx >> 4, kk = idx & 15;
            int gr = row0 + r, gk = mb + kk;
            As[kk][r] = (gr < n && gk < m) ? A[(size_t)gr * m + gk] : 0.0f;
        }
        #pragma unroll
        for (int i = 0; i < 4; i++) {
            int idx = tid + i * 256;
            int kk = idx >> 6, c = idx & 63;
            int gk = mb + kk, gc = col0 + c;
            Ws[kk][c] = (gk < m && gc < k) ? W[(size_t)gk * k + gc] : 0.0f;
        }
        __syncthreads();
        #pragma unroll
        for (int kk = 0; kk < BK; kk++) {
            float a[4], b[4];
            #pragma unroll
            for (int i = 0; i < 4; i++) a[i] = As[kk][ty * 4 + i];
            #pragma unroll
            for (int j = 0; j < 4; j++) b[j] = Ws[kk][tx * 4 + j];
            #pragma unroll
            for (int i = 0; i < 4; i++)
                #pragma unroll
                for (int j = 0; j < 4; j++) acc[i][j] += a[i] * b[j];
        }
        __syncthreads();
    }
    #pragma unroll
    for (int i = 0; i < 4; i++) {
        int gr = row0 + ty * 4 + i;
        if (gr >= n) continue;
        #pragma unroll
        for (int j = 0; j < 4; j++) {
            int gc = col0 + tx * 4 + j;
            if (gc >= k) continue;
            float v = acc[i][j];
            if (GCN2) {
                v = beta * v + (1.0f - beta) * A[(size_t)gr * m + gc];
                v = fmaxf(v, 0.0f);
            }
            C[(size_t)gr * k + gc] = v;
        }
    }
}

// ---------------- GCN propagation ----------------
// out[i] = dinv[i]^2 * h[i] + bias   (self-loop term + bias, full overwrite of out)
template <int D>
__global__ void prop_init(const float* __restrict__ h, float* __restrict__ o,
                          const float* __restrict__ dinv, const float* __restrict__ bias) {
    int i = blockIdx.x * blockDim.x + threadIdx.x;
    if (i >= NN * D) return;
    int node = i / D;
    float w = dinv[node];
    float v = w * w * h[i];
    if (bias) v += bias[i % D];
    o[i] = v;
}

// out[dst] += dinv[src]*dinv[dst] * h[src]   via red.global.add.v4.f32
template <int D4>
__global__ void prop_edges(const float* __restrict__ h, float* __restrict__ o,
                           const int* __restrict__ src, const int* __restrict__ dst,
                           const float* __restrict__ dinv) {
    unsigned t = blockIdx.x * blockDim.x + threadIdx.x;
    if (t >= (unsigned)NE * D4) return;
    unsigned e = t / D4, c = t % D4;
    int s = src[e];
    int d = dst[e];
    float w = dinv[s] * dinv[d];
    float4 v = reinterpret_cast<const float4*>(h)[(size_t)s * D4 + c];
    float4* dp = reinterpret_cast<float4*>(o) + (size_t)d * D4 + c;
    asm volatile("red.global.add.v4.f32 [%0], {%1,%2,%3,%4};"
                 :: "l"(dp), "f"(v.x * w), "f"(v.y * w), "f"(v.z * w), "f"(v.w * w)
                 : "memory");
}

// ---------------- GATv2 ----------------
__device__ __forceinline__ void edge_sd(const int* __restrict__ src, const int* __restrict__ dst,
                                        int e, int& s, int& d) {
    if (e < NE) { s = src[e]; d = dst[e]; }
    else        { s = d = e - NE; }
}
__device__ __forceinline__ unsigned fenc(float f) {
    unsigned u = __float_as_uint(f);
    return (u & 0x80000000u) ? ~u : (u | 0x80000000u);
}
__device__ __forceinline__ float fdec(unsigned u) {
    return (u & 0x80000000u) ? __uint_as_float(u & 0x7fffffffu) : __uint_as_float(~u);
}

// one warp per edge: a[e][h] = sum_c lrelu(xl[s]+xr[d], .2) * att[h][c]
__global__ void gat_a(const float* __restrict__ xl, const float* __restrict__ xr,
                      const int* __restrict__ src, const int* __restrict__ dst,
                      const float* __restrict__ att, float* __restrict__ ea) {
    int e    = (blockIdx.x * blockDim.x + threadIdx.x) >> 5;
    int lane = threadIdx.x & 31;
    if (e >= NE2) return;
    int s, d; edge_sd(src, dst, e, s, d);
    const float* ls = xl + (size_t)s * 128;
    const float* rs = xr + (size_t)d * 128;
    float a[4];
    #pragma unroll
    for (int h = 0; h < 4; h++) {
        float v = ls[h * 32 + lane] + rs[h * 32 + lane];
        v = (v > 0.0f) ? v : 0.2f * v;
        v *= att[h * 32 + lane];
        #pragma unroll
        for (int o = 16; o; o >>= 1) v += __shfl_xor_sync(0xffffffffu, v, o);
        a[h] = v;
    }
    if (lane == 0) reinterpret_cast<float4*>(ea)[e] = make_float4(a[0], a[1], a[2], a[3]);
}

__global__ void gat_amax(const float* __restrict__ ea,
                         const int* __restrict__ src, const int* __restrict__ dst,
                         unsigned* __restrict__ amax) {
    int t = blockIdx.x * blockDim.x + threadIdx.x;
    if (t >= NE2 * 4) return;
    int e = t >> 2, h = t & 3;
    int s, d; edge_sd(src, dst, e, s, d);
    atomicMax(&amax[d * 4 + h], fenc(ea[t]));
}

// ea[t] <- exp(ea[t]-amax[dst]);  asum[dst] += ea[t]
__global__ void gat_expsum(float* __restrict__ ea,
                           const int* __restrict__ src, const int* __restrict__ dst,
                           const unsigned* __restrict__ amax, float* __restrict__ asum) {
    int t = blockIdx.x * blockDim.x + threadIdx.x;
    if (t >= NE2 * 4) return;
    int e = t >> 2, h = t & 3;
    int s, d; edge_sd(src, dst, e, s, d);
    float m  = fdec(amax[d * 4 + h]);
    float ex = expf(ea[t] - m);
    ea[t] = ex;
    atomicAdd(&asum[d * 4 + h], ex);
}

// out[dst] += (ea / (asum[dst]+1e-16)) * xl[src]   (32 float4 chunks per edge)
__global__ void gat_scatter(const float* __restrict__ ea, const float* __restrict__ xl,
                            const int* __restrict__ src, const int* __restrict__ dst,
                            const float* __restrict__ asum, float* __restrict__ out) {
    unsigned t = blockIdx.x * blockDim.x + threadIdx.x;
    if (t >= (unsigned)NE2 * 32) return;
    unsigned e = t >> 5, c = t & 31;
    int s, d; edge_sd(src, dst, (int)e, s, d);
    int h = c >> 3;
    float p = ea[e * 4 + h] / (asum[d * 4 + h] + 1e-16f);
    float4 v = reinterpret_cast<const float4*>(xl)[(size_t)s * 32 + c];
    float4* dp = reinterpret_cast<float4*>(out) + (size_t)d * 32 + c;
    asm volatile("red.global.add.v4.f32 [%0], {%1,%2,%3,%4};"
                 :: "l"(dp), "f"(v.x * p), "f"(v.y * p), "f"(v.z * p), "f"(v.w * p)
                 : "memory");
}

// ---------------- host-side helpers ----------------
static void gemm(const float* A, const float* W, float* C, int n, int m, int k,
                 bool gcn2, float beta) {
    dim3 grid((k + BN - 1) / BN, (n + BM - 1) / BM);
    if (gcn2) gemm_k<true><<<grid, 256>>>(A, W, C, n, m, k, beta);
    else      gemm_k<false><<<grid, 256>>>(A, W, C, n, m, k, 0.0f);
}

static void prop(const float* h, float* o, int D, const float* bias,
                 const float* dinv, const int* src, const int* dst) {
    int nd = NN * D;
    switch (D) {
        case 32:
            prop_init<32><<<divup(nd, 256), 256>>>(h, o, dinv, bias);
            prop_edges<8><<<divup((long long)NE * 8, 256), 256>>>(h, o, src, dst, dinv);
            break;
        case 64:
            prop_init<64><<<divup(nd, 256), 256>>>(h, o, dinv, bias);
            prop_edges<16><<<divup((long long)NE * 16, 256), 256>>>(h, o, src, dst, dinv);
            break;
        case 128:
            prop_init<128><<<divup(nd, 256), 256>>>(h, o, dinv, bias);
            prop_edges<32><<<divup((long long)NE * 32, 256), 256>>>(h, o, src, dst, dinv);
            break;
        case 256:
            prop_init<256><<<divup(nd, 256), 256>>>(h, o, dinv, bias);
            prop_edges<64><<<divup((long long)NE * 64, 256), 256>>>(h, o, src, dst, dinv);
            break;
    }
}

extern "C" void kernel_launch(void* const* d_in, const int* in_sizes, int n_in,
                              void* d_out, int out_size) {
    const float* x   = (const float*)d_in[0];
    const int*   ei32= (const int*)d_in[1];   // edge_index: int32 or int64, detected on-device
    const float* W1 = (const float*)d_in[2];  const float* b1 = (const float*)d_in[3];
    const float* W2 = (const float*)d_in[4];  const float* b2 = (const float*)d_in[5];
    const float* W3 = (const float*)d_in[6];  const float* b3 = (const float*)d_in[7];
    const float* W4 = (const float*)d_in[8];  const float* b4 = (const float*)d_in[9];
    const float* Wl = (const float*)d_in[10]; const float* Wr = (const float*)d_in[11];
    const float* att= (const float*)d_in[12]; const float* bg = (const float*)d_in[13];
    const float* Wc1= (const float*)d_in[14];
    const float* W5 = (const float*)d_in[15]; const float* b5 = (const float*)d_in[16];
    const float* Wc2= (const float*)d_in[17];
    const float* Wo = (const float*)d_in[18]; const float* bo = (const float*)d_in[19];
    float* out = (float*)d_out;

    float *x1, *x2, *A, *B, *C, *D, *ea, *asum, *dinv;
    unsigned* amax;
    int *src, *dst;
    cudaGetSymbolAddress((void**)&x1,   g_x1);
    cudaGetSymbolAddress((void**)&x2,   g_x2);
    cudaGetSymbolAddress((void**)&A,    g_A);
    cudaGetSymbolAddress((void**)&B,    g_B);
    cudaGetSymbolAddress((void**)&C,    g_C);
    cudaGetSymbolAddress((void**)&D,    g_D);
    cudaGetSymbolAddress((void**)&ea,   g_ea);
    cudaGetSymbolAddress((void**)&amax, g_amax);
    cudaGetSymbolAddress((void**)&asum, g_asum);
    cudaGetSymbolAddress((void**)&dinv, g_dinv);
    cudaGetSymbolAddress((void**)&src,  g_src);
    cudaGetSymbolAddress((void**)&dst,  g_dst);

    const float BETA = logf(1.05f);  // log(0.1/2 + 1)

    // ---- edge index dtype detect + convert ----
    k_detect<<<1, 256>>>(ei32);
    k_convert<<<divup(NE, 256), 256>>>(ei32, src, dst);

    // ---- degrees / symmetric norm (deg includes self loop) ----
    k_fill_f<<<divup(NN, 256), 256>>>(dinv, NN, 1.0f);
    k_deg<<<divup(NE, 256), 256>>>(dst, dinv);
    k_rsqrt<<<divup(NN, 256), 256>>>(dinv, NN);

    // ---- x1 = relu(prop(x@W1)+b1) ----
    gemm(x, W1, A, NN, 300, 256, false, 0.0f);
    prop(A, x1, 256, b1, dinv, src, dst);
    k_relu<<<divup(NN * 256, 256), 256>>>(x1, NN * 256);

    // ---- x2 = relu(prop(x1@W2)+b2) ----
    gemm(x1, W2, A, NN, 256, 128, false, 0.0f);
    prop(A, x2, 128, b2, dinv, src, dst);
    k_relu<<<divup(NN * 128, 256), 256>>>(x2, NN * 128);

    // ---- x3 = relu(prop(x2@W3)+b3)  (64) ----
    gemm(x2, W3, A, NN, 128, 64, false, 0.0f);
    prop(A, B, 64, b3, dinv, src, dst);
    k_relu<<<divup(NN * 64, 256), 256>>>(B, NN * 64);

    // ---- x3 = relu(prop(x3@W4)+b4)  (32) ----
    gemm(B, W4, A, NN, 64, 32, false, 0.0f);
    prop(A, B, 32, b4, dinv, src, dst);
    k_relu<<<divup(NN * 32, 256), 256>>>(B, NN * 32);

    // ---- GATv2: x3 = relu(gat(x3)) (128), xl=C, xr=A ----
    gemm(B, Wl, C, NN, 32, 128, false, 0.0f);
    gemm(B, Wr, A, NN, 32, 128, false, 0.0f);
    k_fill_u<<<divup(NN * 4, 256), 256>>>(amax, NN * 4, 0u);
    k_fill_f<<<divup(NN * 4, 256), 256>>>(asum, NN * 4, 0.0f);
    gat_a<<<divup((long long)NE2 * 32, 256), 256>>>(C, A, src, dst, att, ea);
    gat_amax<<<divup(NE2 * 4, 256), 256>>>(ea, src, dst, amax);
    gat_expsum<<<divup(NE2 * 4, 256), 256>>>(ea, src, dst, amax, asum);
    k_binit128<<<divup(NN * 128, 256), 256>>>(D, bg);
    gat_scatter<<<divup((long long)NE2 * 32, 256), 256>>>(ea, C, src, dst, asum, D);
    k_relu<<<divup(NN * 128, 256), 256>>>(D, NN * 128);

    // ---- GCN2 #1 with x0=x2 (128) ----
    prop(D, A, 128, nullptr, dinv, src, dst);
    k_mix<<<divup(NN * 128, 256), 256>>>(A, x2, NN * 128);
    gemm(A, Wc1, B, NN, 128, 128, true, BETA);   // relu fused

    // ---- x3 = relu(prop(x3@W5)+b5) (256) ----
    gemm(B, W5, A, NN, 128, 256, false, 0.0f);
    prop(A, C, 256, b5, dinv, src, dst);
    k_relu<<<divup(NN * 256, 256), 256>>>(C, NN * 256);

    // ---- GCN2 #2 with x0=x1 (256) ----
    prop(C, A, 256, nullptr, dinv, src, dst);
    k_mix<<<divup(NN * 256, 256), 256>>>(A, x1, NN * 256);
    gemm(A, Wc2, B, NN, 256, 256, true, BETA);   // relu fused

    // ---- out = prop(x3@Wo) + bo ----
    gemm(B, Wo, A, NN, 256, 128, false, 0.0f);
    prop(A, out, 128, bo, dinv, src, dst);
}

// round 3
// speedup vs baseline: 1.5650x; 1.5650x over previous
#include <cuda_runtime.h>
#include <math.h>

#define NN 50000
#define NE 800000
#define NE2 850000   /* NE + NN self loops */
#define SCAN_BS 512
#define SCAN_NB ((NN + SCAN_BS - 1) / SCAN_BS)   /* 98 */

// ---------------- device scratch ----------------
__device__ __align__(16) float g_x1[(size_t)NN * 256];
__device__ __align__(16) float g_x2[(size_t)NN * 128];
__device__ __align__(16) float g_A [(size_t)NN * 256];
__device__ __align__(16) float g_B [(size_t)NN * 256];
__device__ __align__(16) float g_C [(size_t)NN * 256];
__device__ __align__(16) float g_D [(size_t)NN * 128];
__device__ __align__(16) float g_ea[(size_t)NE2 * 4];
__device__ float    g_dinv[NN];
__device__ int      g_src[NE];
__device__ int      g_dst[NE];
__device__ int      g_cnt[NN];
__device__ int      g_off[NN + 1];
__device__ int      g_cur[NN];
__device__ int      g_bsum[SCAN_NB + 32];
__device__ int      g_csr_s[NE2];
__device__ int      g_csr_d[NE2];
__device__ float    g_csr_w[NE2];
__device__ int      g_eflag[1];

static inline int divup(long long a, int b) { return (int)((a + b - 1) / b); }

// ---------------- edge-index dtype detection + conversion ----------------
__global__ void k_detect(const int* __restrict__ ei32) {
    __shared__ int cnt;
    if (threadIdx.x == 0) cnt = 0;
    __syncthreads();
    int nz = 0;
    for (int i = threadIdx.x; i < 2048; i += blockDim.x)
        if (ei32[2 * i + 1] != 0) nz++;
    atomicAdd(&cnt, nz);
    __syncthreads();
    if (threadIdx.x == 0) g_eflag[0] = (cnt == 0) ? 1 : 0;  // 1 = int64
}

__global__ void k_convert(const int* __restrict__ ei32,
                          int* __restrict__ src, int* __restrict__ dst) {
    int e = blockIdx.x * blockDim.x + threadIdx.x;
    if (e >= NE) return;
    int is64 = g_eflag[0];
    int s, d;
    if (is64) { s = ei32[2 * e]; d = ei32[2 * (NE + e)]; }
    else      { s = ei32[e];     d = ei32[NE + e]; }
    s = min(max(s, 0), NN - 1);
    d = min(max(d, 0), NN - 1);
    src[e] = s;
    dst[e] = d;
}

// ---------------- CSR build ----------------
__global__ void k_fill_i(int* p, int n, int v) {
    int i = blockIdx.x * blockDim.x + threadIdx.x;
    if (i < n) p[i] = v;
}
__global__ void k_count(const int* __restrict__ dst, int* __restrict__ cnt) {
    int e = blockIdx.x * blockDim.x + threadIdx.x;
    if (e < NE) atomicAdd(&cnt[dst[e]], 1);
}
__global__ void k_dinv(const int* __restrict__ cnt, float* __restrict__ dinv) {
    int i = blockIdx.x * blockDim.x + threadIdx.x;
    if (i < NN) dinv[i] = rsqrtf((float)cnt[i]);
}
__global__ void scan1(const int* __restrict__ cnt, int* __restrict__ bsum) {
    __shared__ int sh[SCAN_BS];
    int i = blockIdx.x * SCAN_BS + threadIdx.x;
    sh[threadIdx.x] = (i < NN) ? cnt[i] : 0;
    __syncthreads();
    for (int s = SCAN_BS / 2; s; s >>= 1) {
        if (threadIdx.x < s) sh[threadIdx.x] += sh[threadIdx.x + s];
        __syncthreads();
    }
    if (threadIdx.x == 0) bsum[blockIdx.x] = sh[0];
}
__global__ void scan2(int* __restrict__ bsum) {  // one block, exclusive scan of SCAN_NB sums
    __shared__ int sh[1024];
    int v = (threadIdx.x < SCAN_NB) ? bsum[threadIdx.x] : 0;
    sh[threadIdx.x] = v;
    __syncthreads();
    for (int o = 1; o < 1024; o <<= 1) {
        int t = (threadIdx.x >= o) ? sh[threadIdx.x - o] : 0;
        __syncthreads();
        sh[threadIdx.x] += t;
        __syncthreads();
    }
    if (threadIdx.x < SCAN_NB) bsum[threadIdx.x] = sh[threadIdx.x] - v;  // exclusive
}
__global__ void scan3(const int* __restrict__ cnt, const int* __restrict__ bsum,
                      int* __restrict__ off) {
    __shared__ int sh[SCAN_BS];
    int i = blockIdx.x * SCAN_BS + threadIdx.x;
    int v = (i < NN) ? cnt[i] : 0;
    sh[threadIdx.x] = v;
    __syncthreads();
    for (int o = 1; o < SCAN_BS; o <<= 1) {
        int t = (threadIdx.x >= o) ? sh[threadIdx.x - o] : 0;
        __syncthreads();
        sh[threadIdx.x] += t;
        __syncthreads();
    }
    if (i <= NN) off[i] = bsum[blockIdx.x] + sh[threadIdx.x] - v;  // exclusive
}
__global__ void k_copy_i(const int* __restrict__ a, int* __restrict__ b, int n) {
    int i = blockIdx.x * blockDim.x + threadIdx.x;
    if (i < n) b[i] = a[i];
}
__global__ void k_bucket(const int* __restrict__ src, const int* __restrict__ dst,
                         const float* __restrict__ dinv, int* __restrict__ cur,
                         int* __restrict__ cs, int* __restrict__ cd, float* __restrict__ cw) {
    int t = blockIdx.x * blockDim.x + threadIdx.x;
    if (t >= NE2) return;
    int s, d;
    if (t < NE) { s = src[t]; d = dst[t]; }
    else        { s = d = t - NE; }
    int pos = atomicAdd(&cur[d], 1);
    cs[pos] = s;
    cd[pos] = d;
    cw[pos] = dinv[s] * dinv[d];
}

// ---------------- GEMM: C[n,k] = A[n,m] @ W[m,k]  (optional GCN2 epilogue + relu) ----------------
#define BM 64
#define BN 64
#define BK 16
template <bool GCN2>
__global__ void gemm_k(const float* __restrict__ A, const float* __restrict__ W,
                       float* __restrict__ C, int n, int m, int k, float beta) {
    __shared__ float As[BK][BM];
    __shared__ float Ws[BK][BN];
    int tid  = threadIdx.x;
    int row0 = blockIdx.y * BM;
    int col0 = blockIdx.x * BN;
    int ty = tid >> 4, tx = tid & 15;
    float acc[4][4] = {};
    for (int mb = 0; mb < m; mb += BK) {
        #pragma unroll
        for (int i = 0; i < 4; i++) {
            int idx = tid + i * 256;
            int r = idx >> 4, kk = idx & 15;
            int gr = row0 + r, gk = mb + kk;
            As[kk][r] = (gr < n && gk < m) ? A[(size_t)gr * m + gk] : 0.0f;
        }
        #pragma unroll
        for (int i = 0; i < 4; i++) {
            int idx = tid + i * 256;
            int kk = idx >> 6, c = idx & 63;
            int gk = mb + kk, gc = col0 + c;
            Ws[kk][c] = (gk < m && gc < k) ? W[(size_t)gk * k + gc] : 0.0f;
        }
        __syncthreads();
        #pragma unroll
        for (int kk = 0; kk < BK; kk++) {
            float a[4], b[4];
            #pragma unroll
            for (int i = 0; i < 4; i++) a[i] = As[kk][ty * 4 + i];
            #pragma unroll
            for (int j = 0; j < 4; j++) b[j] = Ws[kk][tx * 4 + j];
            #pragma unroll
            for (int i = 0; i < 4; i++)
                #pragma unroll
                for (int j = 0; j < 4; j++) acc[i][j] += a[i] * b[j];
        }
        __syncthreads();
    }
    #pragma unroll
    for (int i = 0; i < 4; i++) {
        int gr = row0 + ty * 4 + i;
        if (gr >= n) continue;
        #pragma unroll
        for (int j = 0; j < 4; j++) {
            int gc = col0 + tx * 4 + j;
            if (gc >= k) continue;
            float v = acc[i][j];
            if (GCN2) {
                v = beta * v + (1.0f - beta) * A[(size_t)gr * m + gc];
                v = fmaxf(v, 0.0f);
            }
            C[(size_t)gr * k + gc] = v;
        }
    }
}

// ---------------- pull-based GCN propagation (CSR, no atomics) ----------------
// MODE 0: out = relu(acc + bias)    MODE 1: out = 0.5*(acc + x0)    MODE 2: out = acc + bias
template <int D4, int MODE>
__global__ void prop_pull(const float4* __restrict__ h, float4* __restrict__ o,
                          const float* __restrict__ aux,
                          const int* __restrict__ off, const int* __restrict__ csr_s,
                          const float* __restrict__ csr_w) {
    constexpr int TPN = (D4 < 32) ? D4 : 32;   // threads per node
    constexpr int NPW = 32 / TPN;              // nodes per warp
    constexpr int R   = D4 / TPN;              // float4 per thread
    int gwarp = (blockIdx.x * blockDim.x + threadIdx.x) >> 5;
    int lane  = threadIdx.x & 31;
    int node  = gwarp * NPW + lane / TPN;
    int tl    = lane % TPN;
    if (node >= NN) return;

    float4 acc[R];
    #pragma unroll
    for (int r = 0; r < R; r++) acc[r] = make_float4(0.f, 0.f, 0.f, 0.f);

    int j0 = off[node], j1 = off[node + 1];
    int j = j0;
    for (; j + 1 < j1; j += 2) {
        int   s0 = csr_s[j],     s1 = csr_s[j + 1];
        float w0 = csr_w[j],     w1 = csr_w[j + 1];
        #pragma unroll
        for (int r = 0; r < R; r++) {
            float4 v0 = h[(size_t)s0 * D4 + tl + r * TPN];
            float4 v1 = h[(size_t)s1 * D4 + tl + r * TPN];
            acc[r].x += w0 * v0.x + w1 * v1.x;
            acc[r].y += w0 * v0.y + w1 * v1.y;
            acc[r].z += w0 * v0.z + w1 * v1.z;
            acc[r].w += w0 * v0.w + w1 * v1.w;
        }
    }
    if (j < j1) {
        int s0 = csr_s[j];
        float w0 = csr_w[j];
        #pragma unroll
        for (int r = 0; r < R; r++) {
            float4 v0 = h[(size_t)s0 * D4 + tl + r * TPN];
            acc[r].x += w0 * v0.x; acc[r].y += w0 * v0.y;
            acc[r].z += w0 * v0.z; acc[r].w += w0 * v0.w;
        }
    }

    const float4* aux4 = (const float4*)aux;
    #pragma unroll
    for (int r = 0; r < R; r++) {
        int c = tl + r * TPN;
        float4 v = acc[r];
        if (MODE == 0 || MODE == 2) {
            float4 b = aux4[c];
            v.x += b.x; v.y += b.y; v.z += b.z; v.w += b.w;
            if (MODE == 0) {
                v.x = fmaxf(v.x, 0.f); v.y = fmaxf(v.y, 0.f);
                v.z = fmaxf(v.z, 0.f); v.w = fmaxf(v.w, 0.f);
            }
        } else {  // MODE 1: mix with x0
            float4 x0 = aux4[(size_t)node * D4 + c];
            v.x = 0.5f * (v.x + x0.x); v.y = 0.5f * (v.y + x0.y);
            v.z = 0.5f * (v.z + x0.z); v.w = 0.5f * (v.w + x0.w);
        }
        o[(size_t)node * D4 + c] = v;
    }
}

// ---------------- GATv2 ----------------
// one warp per sorted edge: ea[e][h] = sum_c lrelu(xl[s]+xr[d], .2) * att[h][c]
__global__ void gat_a(const float* __restrict__ xl, const float* __restrict__ xr,
                      const int* __restrict__ cs, const int* __restrict__ cd,
                      const float* __restrict__ att, float* __restrict__ ea) {
    int e    = (blockIdx.x * blockDim.x + threadIdx.x) >> 5;
    int lane = threadIdx.x & 31;
    if (e >= NE2) return;
    int s = cs[e], d = cd[e];
    const float* ls = xl + (size_t)s * 128;
    const float* rs = xr + (size_t)d * 128;
    float a[4];
    #pragma unroll
    for (int h = 0; h < 4; h++) {
        float v = ls[h * 32 + lane] + rs[h * 32 + lane];
        v = (v > 0.0f) ? v : 0.2f * v;
        v *= att[h * 32 + lane];
        #pragma unroll
        for (int o = 16; o; o >>= 1) v += __shfl_xor_sync(0xffffffffu, v, o);
        a[h] = v;
    }
    if (lane == 0) reinterpret_cast<float4*>(ea)[e] = make_float4(a[0], a[1], a[2], a[3]);
}

// one warp per node: softmax over CSR slice + weighted gather + bias + relu
__global__ void gat_node(const float* __restrict__ ea, const float4* __restrict__ xl,
                         const int* __restrict__ off, const int* __restrict__ cs,
                         const float* __restrict__ bg, float4* __restrict__ out) {
    int node = (blockIdx.x * blockDim.x + threadIdx.x) >> 5;
    int lane = threadIdx.x & 31;
    if (node >= NN) return;
    int j0 = off[node], j1 = off[node + 1];
    const float4* ea4 = (const float4*)ea;

    // pass 1: per-head max and exp-sum via warp reductions
    float4 mx = make_float4(-1e30f, -1e30f, -1e30f, -1e30f);
    for (int j = j0 + lane; j < j1; j += 32) {
        float4 a = ea4[j];
        mx.x = fmaxf(mx.x, a.x); mx.y = fmaxf(mx.y, a.y);
        mx.z = fmaxf(mx.z, a.z); mx.w = fmaxf(mx.w, a.w);
    }
    #pragma unroll
    for (int o = 16; o; o >>= 1) {
        mx.x = fmaxf(mx.x, __shfl_xor_sync(0xffffffffu, mx.x, o));
        mx.y = fmaxf(mx.y, __shfl_xor_sync(0xffffffffu, mx.y, o));
        mx.z = fmaxf(mx.z, __shfl_xor_sync(0xffffffffu, mx.z, o));
        mx.w = fmaxf(mx.w, __shfl_xor_sync(0xffffffffu, mx.w, o));
    }
    float4 sm = make_float4(0.f, 0.f, 0.f, 0.f);
    for (int j = j0 + lane; j < j1; j += 32) {
        float4 a = ea4[j];
        sm.x += __expf(a.x - mx.x); sm.y += __expf(a.y - mx.y);
        sm.z += __expf(a.z - mx.z); sm.w += __expf(a.w - mx.w);
    }
    #pragma unroll
    for (int o = 16; o; o >>= 1) {
        sm.x += __shfl_xor_sync(0xffffffffu, sm.x, o);
        sm.y += __shfl_xor_sync(0xffffffffu, sm.y, o);
        sm.z += __shfl_xor_sync(0xffffffffu, sm.z, o);
        sm.w += __shfl_xor_sync(0xffffffffu, sm.w, o);
    }

    // pass 2: weighted gather. lane covers float4 column `lane`, head = lane>>3
    int h = lane >> 3;
    float mxh = (h == 0) ? mx.x : (h == 1) ? mx.y : (h == 2) ? mx.z : mx.w;
    float smh = (h == 0) ? sm.x : (h == 1) ? sm.y : (h == 2) ? sm.z : sm.w;
    float inv = 1.0f / (smh + 1e-16f);
    float4 acc = ((const float4*)bg)[lane];
    for (int j = j0; j < j1; j++) {
        int s = cs[j];
        float p = __expf(ea[(size_t)j * 4 + h] - mxh) * inv;
        float4 v = xl[(size_t)s * 32 + lane];
        acc.x += p * v.x; acc.y += p * v.y; acc.z += p * v.z; acc.w += p * v.w;
    }
    acc.x = fmaxf(acc.x, 0.f); acc.y = fmaxf(acc.y, 0.f);
    acc.z = fmaxf(acc.z, 0.f); acc.w = fmaxf(acc.w, 0.f);
    out[(size_t)node * 32 + lane] = acc;
}

// ---------------- host-side helpers ----------------
static void gemm(const float* A, const float* W, float* C, int n, int m, int k,
                 bool gcn2, float beta) {
    dim3 grid((k + BN - 1) / BN, (n + BM - 1) / BM);
    if (gcn2) gemm_k<true><<<grid, 256>>>(A, W, C, n, m, k, beta);
    else      gemm_k<false><<<grid, 256>>>(A, W, C, n, m, k, 0.0f);
}

template <int D4, int MODE>
static void prop_launch(const float* h, float* o, const float* aux,
                        const int* off, const int* cs, const float* cw) {
    constexpr int NPW = (D4 < 32) ? (32 / D4) : 1;
    int warps = divup(NN, NPW);
    prop_pull<D4, MODE><<<divup((long long)warps * 32, 256), 256>>>(
        (const float4*)h, (float4*)o, aux, off, cs, cw);
}

extern "C" void kernel_launch(void* const* d_in, const int* in_sizes, int n_in,
                              void* d_out, int out_size) {
    const float* x   = (const float*)d_in[0];
    const int*   ei32= (const int*)d_in[1];
    const float* W1 = (const float*)d_in[2];  const float* b1 = (const float*)d_in[3];
    const float* W2 = (const float*)d_in[4];  const float* b2 = (const float*)d_in[5];
    const float* W3 = (const float*)d_in[6];  const float* b3 = (const float*)d_in[7];
    const float* W4 = (const float*)d_in[8];  const float* b4 = (const float*)d_in[9];
    const float* Wl = (const float*)d_in[10]; const float* Wr = (const float*)d_in[11];
    const float* att= (const float*)d_in[12]; const float* bg = (const float*)d_in[13];
    const float* Wc1= (const float*)d_in[14];
    const float* W5 = (const float*)d_in[15]; const float* b5 = (const float*)d_in[16];
    const float* Wc2= (const float*)d_in[17];
    const float* Wo = (const float*)d_in[18]; const float* bo = (const float*)d_in[19];
    float* out = (float*)d_out;

    float *x1, *x2, *A, *B, *C, *D, *ea, *dinv, *cw;
    int *src, *dst, *cnt, *off, *cur, *bsum, *cs, *cd;
    cudaGetSymbolAddress((void**)&x1,   g_x1);
    cudaGetSymbolAddress((void**)&x2,   g_x2);
    cudaGetSymbolAddress((void**)&A,    g_A);
    cudaGetSymbolAddress((void**)&B,    g_B);
    cudaGetSymbolAddress((void**)&C,    g_C);
    cudaGetSymbolAddress((void**)&D,    g_D);
    cudaGetSymbolAddress((void**)&ea,   g_ea);
    cudaGetSymbolAddress((void**)&dinv, g_dinv);
    cudaGetSymbolAddress((void**)&src,  g_src);
    cudaGetSymbolAddress((void**)&dst,  g_dst);
    cudaGetSymbolAddress((void**)&cnt,  g_cnt);
    cudaGetSymbolAddress((void**)&off,  g_off);
    cudaGetSymbolAddress((void**)&cur,  g_cur);
    cudaGetSymbolAddress((void**)&bsum, g_bsum);
    cudaGetSymbolAddress((void**)&cs,   g_csr_s);
    cudaGetSymbolAddress((void**)&cd,   g_csr_d);
    cudaGetSymbolAddress((void**)&cw,   g_csr_w);

    const float BETA = logf(1.05f);

    // ---- edge index detect/convert + CSR build (self-loops included) ----
    k_detect<<<1, 256>>>(ei32);
    k_convert<<<divup(NE, 256), 256>>>(ei32, src, dst);
    k_fill_i<<<divup(NN, 256), 256>>>(cnt, NN, 1);            // self loop
    k_count<<<divup(NE, 256), 256>>>(dst, cnt);
    k_dinv<<<divup(NN, 256), 256>>>(cnt, dinv);
    scan1<<<SCAN_NB, SCAN_BS>>>(cnt, bsum);
    scan2<<<1, 1024>>>(bsum);
    scan3<<<SCAN_NB, SCAN_BS>>>(cnt, bsum, off);
    k_copy_i<<<divup(NN, 256), 256>>>(off, cur, NN);
    k_bucket<<<divup(NE2, 256), 256>>>(src, dst, dinv, cur, cs, cd, cw);

    // ---- x1 = relu(prop(x@W1)+b1) ----
    gemm(x, W1, A, NN, 300, 256, false, 0.0f);
    prop_launch<64, 0>(A, x1, b1, off, cs, cw);

    // ---- x2 = relu(prop(x1@W2)+b2) ----
    gemm(x1, W2, A, NN, 256, 128, false, 0.0f);
    prop_launch<32, 0>(A, x2, b2, off, cs, cw);

    // ---- x3 = relu(prop(x2@W3)+b3)  (64) ----
    gemm(x2, W3, A, NN, 128, 64, false, 0.0f);
    prop_launch<16, 0>(A, B, b3, off, cs, cw);

    // ---- x3 = relu(prop(x3@W4)+b4)  (32) ----
    gemm(B, W4, A, NN, 64, 32, false, 0.0f);
    prop_launch<8, 0>(A, B, b4, off, cs, cw);

    // ---- GATv2: x3 = relu(gat(x3)) (128); xl=C, xr=A ----
    gemm(B, Wl, C, NN, 32, 128, false, 0.0f);
    gemm(B, Wr, A, NN, 32, 128, false, 0.0f);
    gat_a<<<divup((long long)NE2 * 32, 256), 256>>>(C, A, cs, cd, att, ea);
    gat_node<<<divup((long long)NN * 32, 256), 256>>>(ea, (const float4*)C, off, cs, bg, (float4*)D);

    // ---- GCN2 #1 with x0=x2 (128) ----
    prop_launch<32, 1>(D, A, x2, off, cs, cw);               // mix fused
    gemm(A, Wc1, B, NN, 128, 128, true, BETA);               // relu fused

    // ---- x3 = relu(prop(x3@W5)+b5) (256) ----
    gemm(B, W5, A, NN, 128, 256, false, 0.0f);
    prop_launch<64, 0>(A, C, b5, off, cs, cw);

    // ---- GCN2 #2 with x0=x1 (256) ----
    prop_launch<64, 1>(C, A, x1, off, cs, cw);               // mix fused
    gemm(A, Wc2, B, NN, 256, 256, true, BETA);               // relu fused

    // ---- out = prop(x3@Wo) + bo ----
    gemm(B, Wo, A, NN, 256, 128, false, 0.0f);
    prop_launch<32, 2>(A, out, bo, off, cs, cw);
}

// round 4
// speedup vs baseline: 1.8427x; 1.1774x over previous
#include <cuda_runtime.h>
#include <math.h>

#define NN 50000
#define NE 800000
#define NE2 850000   /* NE + NN self loops */
#define SCAN_BS 512
#define SCAN_NB ((NN + SCAN_BS - 1) / SCAN_BS)   /* 98 */

// ---------------- device scratch ----------------
__device__ __align__(16) float g_x1[(size_t)NN * 256];
__device__ __align__(16) float g_x2[(size_t)NN * 128];
__device__ __align__(16) float g_A [(size_t)NN * 256];
__device__ __align__(16) float g_B [(size_t)NN * 256];
__device__ __align__(16) float g_C [(size_t)NN * 256];
__device__ __align__(16) float g_D [(size_t)NN * 128];
__device__ __align__(16) float g_ea[(size_t)NE2 * 4];
__device__ float    g_dinv[NN];
__device__ int      g_src[NE];
__device__ int      g_dst[NE];
__device__ int      g_cnt[NN];
__device__ int      g_off[NN + 1];
__device__ int      g_cur[NN];
__device__ int      g_bsum[SCAN_NB + 32];
__device__ int      g_csr_s[NE2];
__device__ int      g_csr_d[NE2];
__device__ float    g_csr_w[NE2];
__device__ int      g_eflag[1];

static inline int divup(long long a, int b) { return (int)((a + b - 1) / b); }

// ---------------- edge-index dtype detection + conversion ----------------
__global__ void k_detect(const int* __restrict__ ei32) {
    __shared__ int cnt;
    if (threadIdx.x == 0) cnt = 0;
    __syncthreads();
    int nz = 0;
    for (int i = threadIdx.x; i < 2048; i += blockDim.x)
        if (ei32[2 * i + 1] != 0) nz++;
    atomicAdd(&cnt, nz);
    __syncthreads();
    if (threadIdx.x == 0) g_eflag[0] = (cnt == 0) ? 1 : 0;  // 1 = int64
}

__global__ void k_convert(const int* __restrict__ ei32,
                          int* __restrict__ src, int* __restrict__ dst) {
    int e = blockIdx.x * blockDim.x + threadIdx.x;
    if (e >= NE) return;
    int is64 = g_eflag[0];
    int s, d;
    if (is64) { s = ei32[2 * e]; d = ei32[2 * (NE + e)]; }
    else      { s = ei32[e];     d = ei32[NE + e]; }
    s = min(max(s, 0), NN - 1);
    d = min(max(d, 0), NN - 1);
    src[e] = s;
    dst[e] = d;
}

// ---------------- CSR build ----------------
__global__ void k_fill_i(int* p, int n, int v) {
    int i = blockIdx.x * blockDim.x + threadIdx.x;
    if (i < n) p[i] = v;
}
__global__ void k_count(const int* __restrict__ dst, int* __restrict__ cnt) {
    int e = blockIdx.x * blockDim.x + threadIdx.x;
    if (e < NE) atomicAdd(&cnt[dst[e]], 1);
}
__global__ void k_dinv(const int* __restrict__ cnt, float* __restrict__ dinv) {
    int i = blockIdx.x * blockDim.x + threadIdx.x;
    if (i < NN) dinv[i] = rsqrtf((float)cnt[i]);
}
__global__ void scan1(const int* __restrict__ cnt, int* __restrict__ bsum) {
    __shared__ int sh[SCAN_BS];
    int i = blockIdx.x * SCAN_BS + threadIdx.x;
    sh[threadIdx.x] = (i < NN) ? cnt[i] : 0;
    __syncthreads();
    for (int s = SCAN_BS / 2; s; s >>= 1) {
        if (threadIdx.x < s) sh[threadIdx.x] += sh[threadIdx.x + s];
        __syncthreads();
    }
    if (threadIdx.x == 0) bsum[blockIdx.x] = sh[0];
}
__global__ void scan2(int* __restrict__ bsum) {
    __shared__ int sh[1024];
    int v = (threadIdx.x < SCAN_NB) ? bsum[threadIdx.x] : 0;
    sh[threadIdx.x] = v;
    __syncthreads();
    for (int o = 1; o < 1024; o <<= 1) {
        int t = (threadIdx.x >= o) ? sh[threadIdx.x - o] : 0;
        __syncthreads();
        sh[threadIdx.x] += t;
        __syncthreads();
    }
    if (threadIdx.x < SCAN_NB) bsum[threadIdx.x] = sh[threadIdx.x] - v;
}
__global__ void scan3(const int* __restrict__ cnt, const int* __restrict__ bsum,
                      int* __restrict__ off) {
    __shared__ int sh[SCAN_BS];
    int i = blockIdx.x * SCAN_BS + threadIdx.x;
    int v = (i < NN) ? cnt[i] : 0;
    sh[threadIdx.x] = v;
    __syncthreads();
    for (int o = 1; o < SCAN_BS; o <<= 1) {
        int t = (threadIdx.x >= o) ? sh[threadIdx.x - o] : 0;
        __syncthreads();
        sh[threadIdx.x] += t;
        __syncthreads();
    }
    if (i <= NN) off[i] = bsum[blockIdx.x] + sh[threadIdx.x] - v;
}
__global__ void k_copy_i(const int* __restrict__ a, int* __restrict__ b, int n) {
    int i = blockIdx.x * blockDim.x + threadIdx.x;
    if (i < n) b[i] = a[i];
}
__global__ void k_bucket(const int* __restrict__ src, const int* __restrict__ dst,
                         const float* __restrict__ dinv, int* __restrict__ cur,
                         int* __restrict__ cs, int* __restrict__ cd, float* __restrict__ cw) {
    int t = blockIdx.x * blockDim.x + threadIdx.x;
    if (t >= NE2) return;
    int s, d;
    if (t < NE) { s = src[t]; d = dst[t]; }
    else        { s = d = t - NE; }
    int pos = atomicAdd(&cur[d], 1);
    cs[pos] = s;
    cd[pos] = d;
    cw[pos] = dinv[s] * dinv[d];
}

// ---------------- GEMM: C[n,k] = A[n,m] @ W[m,k] ----------------
// 128x128x16 tile, 256 threads, 8x8 per-thread accumulators, float4 smem path.
// requires m % 4 == 0, k % 4 == 0 (true for all calls: 300/256/128/64/32).
#define TM 128
#define TN 128
#define TK 16
#define LDP 132   /* padded row stride in floats (16B aligned, conflict-free) */
template <bool GCN2>
__global__ __launch_bounds__(256) void gemm_k(
    const float* __restrict__ A, const float* __restrict__ W,
    float* __restrict__ C, int n, int m, int k, float beta) {
    __shared__ float As[TK][LDP];
    __shared__ float Ws[TK][LDP];
    int tid  = threadIdx.x;
    int row0 = blockIdx.y * TM;
    int col0 = blockIdx.x * TN;
    int ty = tid >> 4, tx = tid & 15;     // 16x16 thread grid
    int ry = ty * 8, rx = tx * 8;

    float acc[8][8];
    #pragma unroll
    for (int i = 0; i < 8; i++)
        #pragma unroll
        for (int j = 0; j < 8; j++) acc[i][j] = 0.0f;

    for (int mb = 0; mb < m; mb += TK) {
        // load A tile 128 rows x 16 k  (512 float4, 2 per thread)
        #pragma unroll
        for (int i = 0; i < 2; i++) {
            int idx = tid * 2 + i;
            int r = idx >> 2, kq = (idx & 3) * 4;
            int gr = row0 + r, gk = mb + kq;
            float4 v = make_float4(0.f, 0.f, 0.f, 0.f);
            if (gr < n && gk < m)
                v = *reinterpret_cast<const float4*>(&A[(size_t)gr * m + gk]);
            As[kq + 0][r] = v.x;
            As[kq + 1][r] = v.y;
            As[kq + 2][r] = v.z;
            As[kq + 3][r] = v.w;
        }
        // load W tile 16 k x 128 cols (512 float4, 2 per thread)
        #pragma unroll
        for (int i = 0; i < 2; i++) {
            int idx = tid * 2 + i;
            int kk = idx >> 5, cq = (idx & 31) * 4;
            int gk = mb + kk, gc = col0 + cq;
            float4 v = make_float4(0.f, 0.f, 0.f, 0.f);
            if (gk < m && gc < k)
                v = *reinterpret_cast<const float4*>(&W[(size_t)gk * k + gc]);
            *reinterpret_cast<float4*>(&Ws[kk][cq]) = v;
        }
        __syncthreads();
        #pragma unroll
        for (int kk = 0; kk < TK; kk++) {
            float4 a0 = *reinterpret_cast<const float4*>(&As[kk][ry]);
            float4 a1 = *reinterpret_cast<const float4*>(&As[kk][ry + 4]);
            float4 b0 = *reinterpret_cast<const float4*>(&Ws[kk][rx]);
            float4 b1 = *reinterpret_cast<const float4*>(&Ws[kk][rx + 4]);
            float a[8] = {a0.x, a0.y, a0.z, a0.w, a1.x, a1.y, a1.z, a1.w};
            float b[8] = {b0.x, b0.y, b0.z, b0.w, b1.x, b1.y, b1.z, b1.w};
            #pragma unroll
            for (int i = 0; i < 8; i++)
                #pragma unroll
                for (int j = 0; j < 8; j++) acc[i][j] += a[i] * b[j];
        }
        __syncthreads();
    }

    #pragma unroll
    for (int i = 0; i < 8; i++) {
        int gr = row0 + ry + i;
        if (gr >= n) continue;
        #pragma unroll
        for (int jq = 0; jq < 2; jq++) {
            int gc = col0 + rx + jq * 4;
            if (gc >= k) continue;
            float4 v = make_float4(acc[i][jq * 4], acc[i][jq * 4 + 1],
                                   acc[i][jq * 4 + 2], acc[i][jq * 4 + 3]);
            if (GCN2) {
                float4 x0 = *reinterpret_cast<const float4*>(&A[(size_t)gr * m + gc]);
                v.x = fmaxf(beta * v.x + (1.0f - beta) * x0.x, 0.f);
                v.y = fmaxf(beta * v.y + (1.0f - beta) * x0.y, 0.f);
                v.z = fmaxf(beta * v.z + (1.0f - beta) * x0.z, 0.f);
                v.w = fmaxf(beta * v.w + (1.0f - beta) * x0.w, 0.f);
            }
            *reinterpret_cast<float4*>(&C[(size_t)gr * k + gc]) = v;
        }
    }
}

// ---------------- pull-based GCN propagation (CSR, no atomics) ----------------
// MODE 0: out = relu(acc + bias)    MODE 1: out = 0.5*(acc + x0)    MODE 2: out = acc + bias
template <int D4, int MODE>
__global__ void prop_pull(const float4* __restrict__ h, float4* __restrict__ o,
                          const float* __restrict__ aux,
                          const int* __restrict__ off, const int* __restrict__ csr_s,
                          const float* __restrict__ csr_w) {
    constexpr int TPN = (D4 < 32) ? D4 : 32;
    constexpr int NPW = 32 / TPN;
    constexpr int R   = D4 / TPN;
    int gwarp = (blockIdx.x * blockDim.x + threadIdx.x) >> 5;
    int lane  = threadIdx.x & 31;
    int node  = gwarp * NPW + lane / TPN;
    int tl    = lane % TPN;
    if (node >= NN) return;

    float4 acc[R];
    #pragma unroll
    for (int r = 0; r < R; r++) acc[r] = make_float4(0.f, 0.f, 0.f, 0.f);

    int j0 = off[node], j1 = off[node + 1];
    int j = j0;
    for (; j + 1 < j1; j += 2) {
        int   s0 = csr_s[j],     s1 = csr_s[j + 1];
        float w0 = csr_w[j],     w1 = csr_w[j + 1];
        #pragma unroll
        for (int r = 0; r < R; r++) {
            float4 v0 = h[(size_t)s0 * D4 + tl + r * TPN];
            float4 v1 = h[(size_t)s1 * D4 + tl + r * TPN];
            acc[r].x += w0 * v0.x + w1 * v1.x;
            acc[r].y += w0 * v0.y + w1 * v1.y;
            acc[r].z += w0 * v0.z + w1 * v1.z;
            acc[r].w += w0 * v0.w + w1 * v1.w;
        }
    }
    if (j < j1) {
        int s0 = csr_s[j];
        float w0 = csr_w[j];
        #pragma unroll
        for (int r = 0; r < R; r++) {
            float4 v0 = h[(size_t)s0 * D4 + tl + r * TPN];
            acc[r].x += w0 * v0.x; acc[r].y += w0 * v0.y;
            acc[r].z += w0 * v0.z; acc[r].w += w0 * v0.w;
        }
    }

    const float4* aux4 = (const float4*)aux;
    #pragma unroll
    for (int r = 0; r < R; r++) {
        int c = tl + r * TPN;
        float4 v = acc[r];
        if (MODE == 0 || MODE == 2) {
            float4 b = aux4[c];
            v.x += b.x; v.y += b.y; v.z += b.z; v.w += b.w;
            if (MODE == 0) {
                v.x = fmaxf(v.x, 0.f); v.y = fmaxf(v.y, 0.f);
                v.z = fmaxf(v.z, 0.f); v.w = fmaxf(v.w, 0.f);
            }
        } else {
            float4 x0 = aux4[(size_t)node * D4 + c];
            v.x = 0.5f * (v.x + x0.x); v.y = 0.5f * (v.y + x0.y);
            v.z = 0.5f * (v.z + x0.z); v.w = 0.5f * (v.w + x0.w);
        }
        o[(size_t)node * D4 + c] = v;
    }
}

// ---------------- GATv2 ----------------
__global__ void gat_a(const float* __restrict__ xl, const float* __restrict__ xr,
                      const int* __restrict__ cs, const int* __restrict__ cd,
                      const float* __restrict__ att, float* __restrict__ ea) {
    int e    = (blockIdx.x * blockDim.x + threadIdx.x) >> 5;
    int lane = threadIdx.x & 31;
    if (e >= NE2) return;
    int s = cs[e], d = cd[e];
    const float* ls = xl + (size_t)s * 128;
    const float* rs = xr + (size_t)d * 128;
    float a[4];
    #pragma unroll
    for (int h = 0; h < 4; h++) {
        float v = ls[h * 32 + lane] + rs[h * 32 + lane];
        v = (v > 0.0f) ? v : 0.2f * v;
        v *= att[h * 32 + lane];
        #pragma unroll
        for (int o = 16; o; o >>= 1) v += __shfl_xor_sync(0xffffffffu, v, o);
        a[h] = v;
    }
    if (lane == 0) reinterpret_cast<float4*>(ea)[e] = make_float4(a[0], a[1], a[2], a[3]);
}

__global__ void gat_node(const float* __restrict__ ea, const float4* __restrict__ xl,
                         const int* __restrict__ off, const int* __restrict__ cs,
                         const float* __restrict__ bg, float4* __restrict__ out) {
    int node = (blockIdx.x * blockDim.x + threadIdx.x) >> 5;
    int lane = threadIdx.x & 31;
    if (node >= NN) return;
    int j0 = off[node], j1 = off[node + 1];
    const float4* ea4 = (const float4*)ea;

    float4 mx = make_float4(-1e30f, -1e30f, -1e30f, -1e30f);
    for (int j = j0 + lane; j < j1; j += 32) {
        float4 a = ea4[j];
        mx.x = fmaxf(mx.x, a.x); mx.y = fmaxf(mx.y, a.y);
        mx.z = fmaxf(mx.z, a.z); mx.w = fmaxf(mx.w, a.w);
    }
    #pragma unroll
    for (int o = 16; o; o >>= 1) {
        mx.x = fmaxf(mx.x, __shfl_xor_sync(0xffffffffu, mx.x, o));
        mx.y = fmaxf(mx.y, __shfl_xor_sync(0xffffffffu, mx.y, o));
        mx.z = fmaxf(mx.z, __shfl_xor_sync(0xffffffffu, mx.z, o));
        mx.w = fmaxf(mx.w, __shfl_xor_sync(0xffffffffu, mx.w, o));
    }
    float4 sm = make_float4(0.f, 0.f, 0.f, 0.f);
    for (int j = j0 + lane; j < j1; j += 32) {
        float4 a = ea4[j];
        sm.x += __expf(a.x - mx.x); sm.y += __expf(a.y - mx.y);
        sm.z += __expf(a.z - mx.z); sm.w += __expf(a.w - mx.w);
    }
    #pragma unroll
    for (int o = 16; o; o >>= 1) {
        sm.x += __shfl_xor_sync(0xffffffffu, sm.x, o);
        sm.y += __shfl_xor_sync(0xffffffffu, sm.y, o);
        sm.z += __shfl_xor_sync(0xffffffffu, sm.z, o);
        sm.w += __shfl_xor_sync(0xffffffffu, sm.w, o);
    }

    int h = lane >> 3;
    float mxh = (h == 0) ? mx.x : (h == 1) ? mx.y : (h == 2) ? mx.z : mx.w;
    float smh = (h == 0) ? sm.x : (h == 1) ? sm.y : (h == 2) ? sm.z : sm.w;
    float inv = 1.0f / (smh + 1e-16f);
    float4 acc = ((const float4*)bg)[lane];
    for (int j = j0; j < j1; j++) {
        int s = cs[j];
        float p = __expf(ea[(size_t)j * 4 + h] - mxh) * inv;
        float4 v = xl[(size_t)s * 32 + lane];
        acc.x += p * v.x; acc.y += p * v.y; acc.z += p * v.z; acc.w += p * v.w;
    }
    acc.x = fmaxf(acc.x, 0.f); acc.y = fmaxf(acc.y, 0.f);
    acc.z = fmaxf(acc.z, 0.f); acc.w = fmaxf(acc.w, 0.f);
    out[(size_t)node * 32 + lane] = acc;
}

// ---------------- host-side helpers ----------------
static void gemm(const float* A, const float* W, float* C, int n, int m, int k,
                 bool gcn2, float beta) {
    dim3 grid(divup(k, TN), divup(n, TM));
    if (gcn2) gemm_k<true><<<grid, 256>>>(A, W, C, n, m, k, beta);
    else      gemm_k<false><<<grid, 256>>>(A, W, C, n, m, k, 0.0f);
}

template <int D4, int MODE>
static void prop_launch(const float* h, float* o, const float* aux,
                        const int* off, const int* cs, const float* cw) {
    constexpr int NPW = (D4 < 32) ? (32 / D4) : 1;
    int warps = divup(NN, NPW);
    prop_pull<D4, MODE><<<divup((long long)warps * 32, 256), 256>>>(
        (const float4*)h, (float4*)o, aux, off, cs, cw);
}

extern "C" void kernel_launch(void* const* d_in, const int* in_sizes, int n_in,
                              void* d_out, int out_size) {
    const float* x   = (const float*)d_in[0];
    const int*   ei32= (const int*)d_in[1];
    const float* W1 = (const float*)d_in[2];  const float* b1 = (const float*)d_in[3];
    const float* W2 = (const float*)d_in[4];  const float* b2 = (const float*)d_in[5];
    const float* W3 = (const float*)d_in[6];  const float* b3 = (const float*)d_in[7];
    const float* W4 = (const float*)d_in[8];  const float* b4 = (const float*)d_in[9];
    const float* Wl = (const float*)d_in[10]; const float* Wr = (const float*)d_in[11];
    const float* att= (const float*)d_in[12]; const float* bg = (const float*)d_in[13];
    const float* Wc1= (const float*)d_in[14];
    const float* W5 = (const float*)d_in[15]; const float* b5 = (const float*)d_in[16];
    const float* Wc2= (const float*)d_in[17];
    const float* Wo = (const float*)d_in[18]; const float* bo = (const float*)d_in[19];
    float* out = (float*)d_out;

    float *x1, *x2, *A, *B, *C, *D, *ea, *dinv, *cw;
    int *src, *dst, *cnt, *off, *cur, *bsum, *cs, *cd;
    cudaGetSymbolAddress((void**)&x1,   g_x1);
    cudaGetSymbolAddress((void**)&x2,   g_x2);
    cudaGetSymbolAddress((void**)&A,    g_A);
    cudaGetSymbolAddress((void**)&B,    g_B);
    cudaGetSymbolAddress((void**)&C,    g_C);
    cudaGetSymbolAddress((void**)&D,    g_D);
    cudaGetSymbolAddress((void**)&ea,   g_ea);
    cudaGetSymbolAddress((void**)&dinv, g_dinv);
    cudaGetSymbolAddress((void**)&src,  g_src);
    cudaGetSymbolAddress((void**)&dst,  g_dst);
    cudaGetSymbolAddress((void**)&cnt,  g_cnt);
    cudaGetSymbolAddress((void**)&off,  g_off);
    cudaGetSymbolAddress((void**)&cur,  g_cur);
    cudaGetSymbolAddress((void**)&bsum, g_bsum);
    cudaGetSymbolAddress((void**)&cs,   g_csr_s);
    cudaGetSymbolAddress((void**)&cd,   g_csr_d);
    cudaGetSymbolAddress((void**)&cw,   g_csr_w);

    const float BETA = logf(1.05f);

    // ---- edge index detect/convert + CSR build ----
    k_detect<<<1, 256>>>(ei32);
    k_convert<<<divup(NE, 256), 256>>>(ei32, src, dst);
    k_fill_i<<<divup(NN, 256), 256>>>(cnt, NN, 1);
    k_count<<<divup(NE, 256), 256>>>(dst, cnt);
    k_dinv<<<divup(NN, 256), 256>>>(cnt, dinv);
    scan1<<<SCAN_NB, SCAN_BS>>>(cnt, bsum);
    scan2<<<1, 1024>>>(bsum);
    scan3<<<SCAN_NB, SCAN_BS>>>(cnt, bsum, off);
    k_copy_i<<<divup(NN, 256), 256>>>(off, cur, NN);
    k_bucket<<<divup(NE2, 256), 256>>>(src, dst, dinv, cur, cs, cd, cw);

    // ---- x1 = relu(prop(x@W1)+b1) ----
    gemm(x, W1, A, NN, 300, 256, false, 0.0f);
    prop_launch<64, 0>(A, x1, b1, off, cs, cw);

    // ---- x2 = relu(prop(x1@W2)+b2) ----
    gemm(x1, W2, A, NN, 256, 128, false, 0.0f);
    prop_launch<32, 0>(A, x2, b2, off, cs, cw);

    // ---- x3 = relu(prop(x2@W3)+b3)  (64) ----
    gemm(x2, W3, A, NN, 128, 64, false, 0.0f);
    prop_launch<16, 0>(A, B, b3, off, cs, cw);

    // ---- x3 = relu(prop(x3@W4)+b4)  (32) ----
    gemm(B, W4, A, NN, 64, 32, false, 0.0f);
    prop_launch<8, 0>(A, B, b4, off, cs, cw);

    // ---- GATv2 (128); xl=C, xr=A ----
    gemm(B, Wl, C, NN, 32, 128, false, 0.0f);
    gemm(B, Wr, A, NN, 32, 128, false, 0.0f);
    gat_a<<<divup((long long)NE2 * 32, 256), 256>>>(C, A, cs, cd, att, ea);
    gat_node<<<divup((long long)NN * 32, 256), 256>>>(ea, (const float4*)C, off, cs, bg, (float4*)D);

    // ---- GCN2 #1 with x0=x2 (128) ----
    prop_launch<32, 1>(D, A, x2, off, cs, cw);
    gemm(A, Wc1, B, NN, 128, 128, true, BETA);

    // ---- x3 = relu(prop(x3@W5)+b5) (256) ----
    gemm(B, W5, A, NN, 128, 256, false, 0.0f);
    prop_launch<64, 0>(A, C, b5, off, cs, cw);

    // ---- GCN2 #2 with x0=x1 (256) ----
    prop_launch<64, 1>(C, A, x1, off, cs, cw);
    gemm(A, Wc2, B, NN, 256, 256, true, BETA);

    // ---- out = prop(x3@Wo) + bo ----
    gemm(B, Wo, A, NN, 256, 128, false, 0.0f);
    prop_launch<32, 2>(A, out, bo, off, cs, cw);
}

// round 5
// speedup vs baseline: 1.8650x; 1.0121x over previous
#include <cuda_runtime.h>
#include <math.h>

#define NN 50000
#define NE 800000
#define NE2 850000   /* NE + NN self loops */
#define SCAN_BS 512
#define SCAN_NB ((NN + SCAN_BS - 1) / SCAN_BS)   /* 98 */

// ---------------- device scratch ----------------
__device__ __align__(16) float g_x1[(size_t)NN * 256];
__device__ __align__(16) float g_x2[(size_t)NN * 128];
__device__ __align__(16) float g_A [(size_t)NN * 256];
__device__ __align__(16) float g_B [(size_t)NN * 256];
__device__ __align__(16) float g_C [(size_t)NN * 256];
__device__ __align__(16) float g_D [(size_t)NN * 128];
__device__ __align__(16) float g_ea[(size_t)NE2 * 4];
__device__ float    g_dinv[NN];
__device__ int      g_src[NE];
__device__ int      g_dst[NE];
__device__ int      g_cnt[NN];
__device__ int      g_off[NN + 1];
__device__ int      g_cur[NN];
__device__ int      g_bsum[SCAN_NB + 32];
__device__ int      g_csr_s[NE2];
__device__ int      g_csr_d[NE2];
__device__ float    g_csr_w[NE2];
__device__ int      g_eflag[1];

static inline int divup(long long a, int b) { return (int)((a + b - 1) / b); }

// ---------------- edge-index dtype detection + conversion ----------------
__global__ void k_detect(const int* __restrict__ ei32) {
    __shared__ int cnt;
    if (threadIdx.x == 0) cnt = 0;
    __syncthreads();
    int nz = 0;
    for (int i = threadIdx.x; i < 2048; i += blockDim.x)
        if (ei32[2 * i + 1] != 0) nz++;
    atomicAdd(&cnt, nz);
    __syncthreads();
    if (threadIdx.x == 0) g_eflag[0] = (cnt == 0) ? 1 : 0;  // 1 = int64
}

__global__ void k_convert(const int* __restrict__ ei32,
                          int* __restrict__ src, int* __restrict__ dst) {
    int e = blockIdx.x * blockDim.x + threadIdx.x;
    if (e >= NE) return;
    int is64 = g_eflag[0];
    int s, d;
    if (is64) { s = ei32[2 * e]; d = ei32[2 * (NE + e)]; }
    else      { s = ei32[e];     d = ei32[NE + e]; }
    s = min(max(s, 0), NN - 1);
    d = min(max(d, 0), NN - 1);
    src[e] = s;
    dst[e] = d;
}

// ---------------- CSR build ----------------
__global__ void k_fill_i(int* p, int n, int v) {
    int i = blockIdx.x * blockDim.x + threadIdx.x;
    if (i < n) p[i] = v;
}
__global__ void k_count(const int* __restrict__ dst, int* __restrict__ cnt) {
    int e = blockIdx.x * blockDim.x + threadIdx.x;
    if (e < NE) atomicAdd(&cnt[dst[e]], 1);
}
__global__ void k_dinv(const int* __restrict__ cnt, float* __restrict__ dinv) {
    int i = blockIdx.x * blockDim.x + threadIdx.x;
    if (i < NN) dinv[i] = rsqrtf((float)cnt[i]);
}
__global__ void scan1(const int* __restrict__ cnt, int* __restrict__ bsum) {
    __shared__ int sh[SCAN_BS];
    int i = blockIdx.x * SCAN_BS + threadIdx.x;
    sh[threadIdx.x] = (i < NN) ? cnt[i] : 0;
    __syncthreads();
    for (int s = SCAN_BS / 2; s; s >>= 1) {
        if (threadIdx.x < s) sh[threadIdx.x] += sh[threadIdx.x + s];
        __syncthreads();
    }
    if (threadIdx.x == 0) bsum[blockIdx.x] = sh[0];
}
__global__ void scan2(int* __restrict__ bsum) {
    __shared__ int sh[1024];
    int v = (threadIdx.x < SCAN_NB) ? bsum[threadIdx.x] : 0;
    sh[threadIdx.x] = v;
    __syncthreads();
    for (int o = 1; o < 1024; o <<= 1) {
        int t = (threadIdx.x >= o) ? sh[threadIdx.x - o] : 0;
        __syncthreads();
        sh[threadIdx.x] += t;
        __syncthreads();
    }
    if (threadIdx.x < SCAN_NB) bsum[threadIdx.x] = sh[threadIdx.x] - v;
}
__global__ void scan3(const int* __restrict__ cnt, const int* __restrict__ bsum,
                      int* __restrict__ off) {
    __shared__ int sh[SCAN_BS];
    int i = blockIdx.x * SCAN_BS + threadIdx.x;
    int v = (i < NN) ? cnt[i] : 0;
    sh[threadIdx.x] = v;
    __syncthreads();
    for (int o = 1; o < SCAN_BS; o <<= 1) {
        int t = (threadIdx.x >= o) ? sh[threadIdx.x - o] : 0;
        __syncthreads();
        sh[threadIdx.x] += t;
        __syncthreads();
    }
    if (i <= NN) off[i] = bsum[blockIdx.x] + sh[threadIdx.x] - v;
}
__global__ void k_copy_i(const int* __restrict__ a, int* __restrict__ b, int n) {
    int i = blockIdx.x * blockDim.x + threadIdx.x;
    if (i < n) b[i] = a[i];
}
__global__ void k_bucket(const int* __restrict__ src, const int* __restrict__ dst,
                         const float* __restrict__ dinv, int* __restrict__ cur,
                         int* __restrict__ cs, int* __restrict__ cd, float* __restrict__ cw) {
    int t = blockIdx.x * blockDim.x + threadIdx.x;
    if (t >= NE2) return;
    int s, d;
    if (t < NE) { s = src[t]; d = dst[t]; }
    else        { s = d = t - NE; }
    int pos = atomicAdd(&cur[d], 1);
    cs[pos] = s;
    cd[pos] = d;
    cw[pos] = dinv[s] * dinv[d];
}

// ---------------- GEMM: C[n,k] = A[n,m] @ W[m,k] ----------------
// 128x128x16 tile, 256 threads, 8x8 accumulators, double-buffered smem,
// register-prefetch of the next tile under the FFMA block.
// EPI: 0 = none, 1 = GCN2 (relu((1-b)A + b*AW), m==k), 2 = relu(AW + bias)
#define TM 128
#define TN 128
#define TK 16
#define LDP 132
template <int EPI>
__global__ __launch_bounds__(256) void gemm_k(
    const float* __restrict__ A, const float* __restrict__ W,
    float* __restrict__ C, int n, int m, int k, float beta,
    const float* __restrict__ bias) {
    __shared__ float As[2][TK][LDP];
    __shared__ float Ws[2][TK][LDP];
    const int tid  = threadIdx.x;
    const int row0 = blockIdx.y * TM;
    const int col0 = blockIdx.x * TN;
    const int ty = tid >> 4, tx = tid & 15;
    const int ry = ty * 8, rx = tx * 8;

    const int a_r0  = (tid * 2) >> 2,        a_r1  = (tid * 2 + 1) >> 2;
    const int a_kq0 = ((tid * 2) & 3) * 4,   a_kq1 = ((tid * 2 + 1) & 3) * 4;
    const int w_kk0 = (tid * 2) >> 5,        w_kk1 = (tid * 2 + 1) >> 5;
    const int w_cq0 = ((tid * 2) & 31) * 4,  w_cq1 = ((tid * 2 + 1) & 31) * 4;

    float acc[8][8];
    #pragma unroll
    for (int i = 0; i < 8; i++)
        #pragma unroll
        for (int j = 0; j < 8; j++) acc[i][j] = 0.0f;

    float4 pa0, pa1, pw0, pw1;
    const float4 Z = make_float4(0.f, 0.f, 0.f, 0.f);

    // prologue: tile 0 -> buf 0
    {
        int gr0 = row0 + a_r0, gr1 = row0 + a_r1;
        pa0 = (gr0 < n && a_kq0 < m) ? *(const float4*)&A[(size_t)gr0 * m + a_kq0] : Z;
        pa1 = (gr1 < n && a_kq1 < m) ? *(const float4*)&A[(size_t)gr1 * m + a_kq1] : Z;
        int gc0 = col0 + w_cq0, gc1 = col0 + w_cq1;
        pw0 = (w_kk0 < m && gc0 < k) ? *(const float4*)&W[(size_t)w_kk0 * k + gc0] : Z;
        pw1 = (w_kk1 < m && gc1 < k) ? *(const float4*)&W[(size_t)w_kk1 * k + gc1] : Z;
        As[0][a_kq0 + 0][a_r0] = pa0.x; As[0][a_kq0 + 1][a_r0] = pa0.y;
        As[0][a_kq0 + 2][a_r0] = pa0.z; As[0][a_kq0 + 3][a_r0] = pa0.w;
        As[0][a_kq1 + 0][a_r1] = pa1.x; As[0][a_kq1 + 1][a_r1] = pa1.y;
        As[0][a_kq1 + 2][a_r1] = pa1.z; As[0][a_kq1 + 3][a_r1] = pa1.w;
        *(float4*)&Ws[0][w_kk0][w_cq0] = pw0;
        *(float4*)&Ws[0][w_kk1][w_cq1] = pw1;
        __syncthreads();
    }

    const int nt = (m + TK - 1) / TK;
    for (int t = 0; t < nt; t++) {
        const int buf = t & 1;
        if (t + 1 < nt) {                     // prefetch next tile into regs
            int mb = (t + 1) * TK;
            int gr0 = row0 + a_r0, gr1 = row0 + a_r1;
            int gk0 = mb + a_kq0,  gk1 = mb + a_kq1;
            pa0 = (gr0 < n && gk0 < m) ? *(const float4*)&A[(size_t)gr0 * m + gk0] : Z;
            pa1 = (gr1 < n && gk1 < m) ? *(const float4*)&A[(size_t)gr1 * m + gk1] : Z;
            int wk0 = mb + w_kk0, wk1 = mb + w_kk1;
            int gc0 = col0 + w_cq0, gc1 = col0 + w_cq1;
            pw0 = (wk0 < m && gc0 < k) ? *(const float4*)&W[(size_t)wk0 * k + gc0] : Z;
            pw1 = (wk1 < m && gc1 < k) ? *(const float4*)&W[(size_t)wk1 * k + gc1] : Z;
        }
        #pragma unroll
        for (int kk = 0; kk < TK; kk++) {
            float4 a0 = *(const float4*)&As[buf][kk][ry];
            float4 a1 = *(const float4*)&As[buf][kk][ry + 4];
            float4 b0 = *(const float4*)&Ws[buf][kk][rx];
            float4 b1 = *(const float4*)&Ws[buf][kk][rx + 4];
            float a[8] = {a0.x, a0.y, a0.z, a0.w, a1.x, a1.y, a1.z, a1.w};
            float b[8] = {b0.x, b0.y, b0.z, b0.w, b1.x, b1.y, b1.z, b1.w};
            #pragma unroll
            for (int i = 0; i < 8; i++)
                #pragma unroll
                for (int j = 0; j < 8; j++) acc[i][j] += a[i] * b[j];
        }
        if (t + 1 < nt) {                     // store prefetched tile -> other buf
            const int nb = buf ^ 1;
            As[nb][a_kq0 + 0][a_r0] = pa0.x; As[nb][a_kq0 + 1][a_r0] = pa0.y;
            As[nb][a_kq0 + 2][a_r0] = pa0.z; As[nb][a_kq0 + 3][a_r0] = pa0.w;
            As[nb][a_kq1 + 0][a_r1] = pa1.x; As[nb][a_kq1 + 1][a_r1] = pa1.y;
            As[nb][a_kq1 + 2][a_r1] = pa1.z; As[nb][a_kq1 + 3][a_r1] = pa1.w;
            *(float4*)&Ws[nb][w_kk0][w_cq0] = pw0;
            *(float4*)&Ws[nb][w_kk1][w_cq1] = pw1;
            __syncthreads();
        }
    }

    #pragma unroll
    for (int i = 0; i < 8; i++) {
        int gr = row0 + ry + i;
        if (gr >= n) continue;
        #pragma unroll
        for (int jq = 0; jq < 2; jq++) {
            int gc = col0 + rx + jq * 4;
            if (gc >= k) continue;
            float4 v = make_float4(acc[i][jq * 4], acc[i][jq * 4 + 1],
                                   acc[i][jq * 4 + 2], acc[i][jq * 4 + 3]);
            if (EPI == 1) {
                float4 x0 = *(const float4*)&A[(size_t)gr * m + gc];
                v.x = fmaxf(beta * v.x + (1.0f - beta) * x0.x, 0.f);
                v.y = fmaxf(beta * v.y + (1.0f - beta) * x0.y, 0.f);
                v.z = fmaxf(beta * v.z + (1.0f - beta) * x0.z, 0.f);
                v.w = fmaxf(beta * v.w + (1.0f - beta) * x0.w, 0.f);
            } else if (EPI == 2) {
                float4 b = *(const float4*)&bias[gc];
                v.x = fmaxf(v.x + b.x, 0.f); v.y = fmaxf(v.y + b.y, 0.f);
                v.z = fmaxf(v.z + b.z, 0.f); v.w = fmaxf(v.w + b.w, 0.f);
            }
            *(float4*)&C[(size_t)gr * k + gc] = v;
        }
    }
}

// ---------------- pull-based GCN propagation (CSR, no atomics) ----------------
// MODE 0: relu(acc+bias)  MODE 1: 0.5*(acc+x0)  MODE 2: acc+bias  MODE 3: acc
template <int D4, int MODE>
__global__ void prop_pull(const float4* __restrict__ h, float4* __restrict__ o,
                          const float* __restrict__ aux,
                          const int* __restrict__ off, const int* __restrict__ csr_s,
                          const float* __restrict__ csr_w) {
    constexpr int TPN = (D4 < 32) ? D4 : 32;
    constexpr int NPW = 32 / TPN;
    constexpr int R   = D4 / TPN;
    int gwarp = (blockIdx.x * blockDim.x + threadIdx.x) >> 5;
    int lane  = threadIdx.x & 31;
    int node  = gwarp * NPW + lane / TPN;
    int tl    = lane % TPN;
    if (node >= NN) return;

    float4 acc[R];
    #pragma unroll
    for (int r = 0; r < R; r++) acc[r] = make_float4(0.f, 0.f, 0.f, 0.f);

    int j0 = off[node], j1 = off[node + 1];
    int j = j0;
    for (; j + 1 < j1; j += 2) {
        int   s0 = csr_s[j],     s1 = csr_s[j + 1];
        float w0 = csr_w[j],     w1 = csr_w[j + 1];
        #pragma unroll
        for (int r = 0; r < R; r++) {
            float4 v0 = h[(size_t)s0 * D4 + tl + r * TPN];
            float4 v1 = h[(size_t)s1 * D4 + tl + r * TPN];
            acc[r].x += w0 * v0.x + w1 * v1.x;
            acc[r].y += w0 * v0.y + w1 * v1.y;
            acc[r].z += w0 * v0.z + w1 * v1.z;
            acc[r].w += w0 * v0.w + w1 * v1.w;
        }
    }
    if (j < j1) {
        int s0 = csr_s[j];
        float w0 = csr_w[j];
        #pragma unroll
        for (int r = 0; r < R; r++) {
            float4 v0 = h[(size_t)s0 * D4 + tl + r * TPN];
            acc[r].x += w0 * v0.x; acc[r].y += w0 * v0.y;
            acc[r].z += w0 * v0.z; acc[r].w += w0 * v0.w;
        }
    }

    const float4* aux4 = (const float4*)aux;
    #pragma unroll
    for (int r = 0; r < R; r++) {
        int c = tl + r * TPN;
        float4 v = acc[r];
        if (MODE == 0 || MODE == 2) {
            float4 b = aux4[c];
            v.x += b.x; v.y += b.y; v.z += b.z; v.w += b.w;
            if (MODE == 0) {
                v.x = fmaxf(v.x, 0.f); v.y = fmaxf(v.y, 0.f);
                v.z = fmaxf(v.z, 0.f); v.w = fmaxf(v.w, 0.f);
            }
        } else if (MODE == 1) {
            float4 x0 = aux4[(size_t)node * D4 + c];
            v.x = 0.5f * (v.x + x0.x); v.y = 0.5f * (v.y + x0.y);
            v.z = 0.5f * (v.z + x0.z); v.w = 0.5f * (v.w + x0.w);
        }
        o[(size_t)node * D4 + c] = v;
    }
}

// ---------------- GATv2 ----------------
__global__ void gat_a(const float* __restrict__ xl, const float* __restrict__ xr,
                      const int* __restrict__ cs, const int* __restrict__ cd,
                      const float* __restrict__ att, float* __restrict__ ea) {
    int e    = (blockIdx.x * blockDim.x + threadIdx.x) >> 5;
    int lane = threadIdx.x & 31;
    if (e >= NE2) return;
    int s = cs[e], d = cd[e];
    const float* ls = xl + (size_t)s * 128;
    const float* rs = xr + (size_t)d * 128;
    float a[4];
    #pragma unroll
    for (int h = 0; h < 4; h++) {
        float v = ls[h * 32 + lane] + rs[h * 32 + lane];
        v = (v > 0.0f) ? v : 0.2f * v;
        v *= att[h * 32 + lane];
        #pragma unroll
        for (int o = 16; o; o >>= 1) v += __shfl_xor_sync(0xffffffffu, v, o);
        a[h] = v;
    }
    if (lane == 0) reinterpret_cast<float4*>(ea)[e] = make_float4(a[0], a[1], a[2], a[3]);
}

__global__ void gat_node(const float* __restrict__ ea, const float4* __restrict__ xl,
                         const int* __restrict__ off, const int* __restrict__ cs,
                         const float* __restrict__ bg, float4* __restrict__ out) {
    int node = (blockIdx.x * blockDim.x + threadIdx.x) >> 5;
    int lane = threadIdx.x & 31;
    if (node >= NN) return;
    int j0 = off[node], j1 = off[node + 1];
    const float4* ea4 = (const float4*)ea;

    float4 mx = make_float4(-1e30f, -1e30f, -1e30f, -1e30f);
    for (int j = j0 + lane; j < j1; j += 32) {
        float4 a = ea4[j];
        mx.x = fmaxf(mx.x, a.x); mx.y = fmaxf(mx.y, a.y);
        mx.z = fmaxf(mx.z, a.z); mx.w = fmaxf(mx.w, a.w);
    }
    #pragma unroll
    for (int o = 16; o; o >>= 1) {
        mx.x = fmaxf(mx.x, __shfl_xor_sync(0xffffffffu, mx.x, o));
        mx.y = fmaxf(mx.y, __shfl_xor_sync(0xffffffffu, mx.y, o));
        mx.z = fmaxf(mx.z, __shfl_xor_sync(0xffffffffu, mx.z, o));
        mx.w = fmaxf(mx.w, __shfl_xor_sync(0xffffffffu, mx.w, o));
    }
    float4 sm = make_float4(0.f, 0.f, 0.f, 0.f);
    for (int j = j0 + lane; j < j1; j += 32) {
        float4 a = ea4[j];
        sm.x += __expf(a.x - mx.x); sm.y += __expf(a.y - mx.y);
        sm.z += __expf(a.z - mx.z); sm.w += __expf(a.w - mx.w);
    }
    #pragma unroll
    for (int o = 16; o; o >>= 1) {
        sm.x += __shfl_xor_sync(0xffffffffu, sm.x, o);
        sm.y += __shfl_xor_sync(0xffffffffu, sm.y, o);
        sm.z += __shfl_xor_sync(0xffffffffu, sm.z, o);
        sm.w += __shfl_xor_sync(0xffffffffu, sm.w, o);
    }

    int h = lane >> 3;
    float mxh = (h == 0) ? mx.x : (h == 1) ? mx.y : (h == 2) ? mx.z : mx.w;
    float smh = (h == 0) ? sm.x : (h == 1) ? sm.y : (h == 2) ? sm.z : sm.w;
    float inv = 1.0f / (smh + 1e-16f);
    float4 acc = ((const float4*)bg)[lane];
    for (int j = j0; j < j1; j++) {
        int s = cs[j];
        float p = __expf(ea[(size_t)j * 4 + h] - mxh) * inv;
        float4 v = xl[(size_t)s * 32 + lane];
        acc.x += p * v.x; acc.y += p * v.y; acc.z += p * v.z; acc.w += p * v.w;
    }
    acc.x = fmaxf(acc.x, 0.f); acc.y = fmaxf(acc.y, 0.f);
    acc.z = fmaxf(acc.z, 0.f); acc.w = fmaxf(acc.w, 0.f);
    out[(size_t)node * 32 + lane] = acc;
}

// ---------------- host-side helpers ----------------
static void gemm(const float* A, const float* W, float* C, int n, int m, int k,
                 int epi, float beta, const float* bias) {
    dim3 grid(divup(k, TN), divup(n, TM));
    if (epi == 1)      gemm_k<1><<<grid, 256>>>(A, W, C, n, m, k, beta, nullptr);
    else if (epi == 2) gemm_k<2><<<grid, 256>>>(A, W, C, n, m, k, 0.0f, bias);
    else               gemm_k<0><<<grid, 256>>>(A, W, C, n, m, k, 0.0f, nullptr);
}

template <int D4, int MODE>
static void prop_launch(const float* h, float* o, const float* aux,
                        const int* off, const int* cs, const float* cw) {
    constexpr int NPW = (D4 < 32) ? (32 / D4) : 1;
    int warps = divup(NN, NPW);
    prop_pull<D4, MODE><<<divup((long long)warps * 32, 256), 256>>>(
        (const float4*)h, (float4*)o, aux, off, cs, cw);
}

extern "C" void kernel_launch(void* const* d_in, const int* in_sizes, int n_in,
                              void* d_out, int out_size) {
    const float* x   = (const float*)d_in[0];
    const int*   ei32= (const int*)d_in[1];
    const float* W1 = (const float*)d_in[2];  const float* b1 = (const float*)d_in[3];
    const float* W2 = (const float*)d_in[4];  const float* b2 = (const float*)d_in[5];
    const float* W3 = (const float*)d_in[6];  const float* b3 = (const float*)d_in[7];
    const float* W4 = (const float*)d_in[8];  const float* b4 = (const float*)d_in[9];
    const float* Wl = (const float*)d_in[10]; const float* Wr = (const float*)d_in[11];
    const float* att= (const float*)d_in[12]; const float* bg = (const float*)d_in[13];
    const float* Wc1= (const float*)d_in[14];
    const float* W5 = (const float*)d_in[15]; const float* b5 = (const float*)d_in[16];
    const float* Wc2= (const float*)d_in[17];
    const float* Wo = (const float*)d_in[18]; const float* bo = (const float*)d_in[19];
    float* out = (float*)d_out;

    float *x1, *x2, *A, *B, *C, *D, *ea, *dinv, *cw;
    int *src, *dst, *cnt, *off, *cur, *bsum, *cs, *cd;
    cudaGetSymbolAddress((void**)&x1,   g_x1);
    cudaGetSymbolAddress((void**)&x2,   g_x2);
    cudaGetSymbolAddress((void**)&A,    g_A);
    cudaGetSymbolAddress((void**)&B,    g_B);
    cudaGetSymbolAddress((void**)&C,    g_C);
    cudaGetSymbolAddress((void**)&D,    g_D);
    cudaGetSymbolAddress((void**)&ea,   g_ea);
    cudaGetSymbolAddress((void**)&dinv, g_dinv);
    cudaGetSymbolAddress((void**)&src,  g_src);
    cudaGetSymbolAddress((void**)&dst,  g_dst);
    cudaGetSymbolAddress((void**)&cnt,  g_cnt);
    cudaGetSymbolAddress((void**)&off,  g_off);
    cudaGetSymbolAddress((void**)&cur,  g_cur);
    cudaGetSymbolAddress((void**)&bsum, g_bsum);
    cudaGetSymbolAddress((void**)&cs,   g_csr_s);
    cudaGetSymbolAddress((void**)&cd,   g_csr_d);
    cudaGetSymbolAddress((void**)&cw,   g_csr_w);

    const float BETA = logf(1.05f);

    // ---- CSR head (launches 1-5), then gemm1 as 6th launch (ncu -s 5 -c 1 target) ----
    k_detect<<<1, 256>>>(ei32);                               // 1
    k_convert<<<divup(NE, 256), 256>>>(ei32, src, dst);       // 2
    k_fill_i<<<divup(NN, 256), 256>>>(cnt, NN, 1);            // 3
    k_count<<<divup(NE, 256), 256>>>(dst, cnt);               // 4
    k_dinv<<<divup(NN, 256), 256>>>(cnt, dinv);               // 5
    gemm(x, W1, A, NN, 300, 256, 0, 0.0f, nullptr);           // 6  <- profiled
    scan1<<<SCAN_NB, SCAN_BS>>>(cnt, bsum);                   // 7
    scan2<<<1, 1024>>>(bsum);
    scan3<<<SCAN_NB, SCAN_BS>>>(cnt, bsum, off);
    k_copy_i<<<divup(NN, 256), 256>>>(off, cur, NN);
    k_bucket<<<divup(NE2, 256), 256>>>(src, dst, dinv, cur, cs, cd, cw);

    // ---- x1 = relu(prop(x@W1)+b1) ----
    prop_launch<64, 0>(A, x1, b1, off, cs, cw);

    // ---- x2 = relu(prop(x1@W2)+b2) ----
    gemm(x1, W2, A, NN, 256, 128, 0, 0.0f, nullptr);
    prop_launch<32, 0>(A, x2, b2, off, cs, cw);

    // ---- x3 = relu(prop(x2@W3)+b3)  (64) ----
    gemm(x2, W3, A, NN, 128, 64, 0, 0.0f, nullptr);
    prop_launch<16, 0>(A, B, b3, off, cs, cw);

    // ---- x3 = relu(prop(x3@W4)+b4)  (32) ----
    gemm(B, W4, A, NN, 64, 32, 0, 0.0f, nullptr);
    prop_launch<8, 0>(A, B, b4, off, cs, cw);

    // ---- GATv2 (128); xl=C, xr=A ----
    gemm(B, Wl, C, NN, 32, 128, 0, 0.0f, nullptr);
    gemm(B, Wr, A, NN, 32, 128, 0, 0.0f, nullptr);
    gat_a<<<divup((long long)NE2 * 32, 256), 256>>>(C, A, cs, cd, att, ea);
    gat_node<<<divup((long long)NN * 32, 256), 256>>>(ea, (const float4*)C, off, cs, bg, (float4*)D);

    // ---- GCN2 #1 with x0=x2 (128) ----
    prop_launch<32, 1>(D, A, x2, off, cs, cw);
    gemm(A, Wc1, B, NN, 128, 128, 1, BETA, nullptr);

    // ---- x3 = relu(prop(B)@W5 + b5)  (prop commuted to 128-d!) ----
    prop_launch<32, 3>(B, A, nullptr, off, cs, cw);          // raw prop at 128
    gemm(A, W5, C, NN, 128, 256, 2, 0.0f, b5);               // bias+relu fused

    // ---- GCN2 #2 with x0=x1 (256) ----
    prop_launch<64, 1>(C, A, x1, off, cs, cw);
    gemm(A, Wc2, B, NN, 256, 256, 1, BETA, nullptr);

    // ---- out = prop(x3@Wo) + bo ----
    gemm(B, Wo, A, NN, 256, 128, 0, 0.0f, nullptr);
    prop_launch<32, 2>(A, out, bo, off, cs, cw);
}

// round 6
// speedup vs baseline: 1.8896x; 1.0132x over previous
#include <cuda_runtime.h>
#include <math.h>

#define NN 50000
#define NE 800000
#define NE2 850000   /* NE + NN self loops */
#define SCAN_BS 512
#define SCAN_NB ((NN + SCAN_BS - 1) / SCAN_BS)   /* 98 */

// ---------------- device scratch ----------------
__device__ __align__(16) float g_x1[(size_t)NN * 256];
__device__ __align__(16) float g_x2[(size_t)NN * 128];
__device__ __align__(16) float g_A [(size_t)NN * 256];
__device__ __align__(16) float g_B [(size_t)NN * 256];
__device__ __align__(16) float g_C [(size_t)NN * 256];
__device__ __align__(16) float g_D [(size_t)NN * 128];
__device__ __align__(16) float g_ea[(size_t)NE2 * 4];
__device__ __align__(16) float g_amax[(size_t)NN * 4];
__device__ __align__(16) float g_asum[(size_t)NN * 4];
__device__ float    g_dinv[NN];
__device__ int      g_src[NE];
__device__ int      g_dst[NE];
__device__ int      g_cnt[NN];
__device__ int      g_off[NN + 1];
__device__ int      g_cur[NN];
__device__ int      g_bsum[SCAN_NB + 32];
__device__ int      g_csr_s[NE2];
__device__ float    g_csr_w[NE2];
__device__ int      g_eflag[1];

static inline int divup(long long a, int b) { return (int)((a + b - 1) / b); }

// ---------------- edge-index dtype detection + conversion ----------------
__global__ void k_detect(const int* __restrict__ ei32) {
    __shared__ int cnt;
    if (threadIdx.x == 0) cnt = 0;
    __syncthreads();
    int nz = 0;
    for (int i = threadIdx.x; i < 2048; i += blockDim.x)
        if (ei32[2 * i + 1] != 0) nz++;
    atomicAdd(&cnt, nz);
    __syncthreads();
    if (threadIdx.x == 0) g_eflag[0] = (cnt == 0) ? 1 : 0;  // 1 = int64
}

__global__ void k_convert(const int* __restrict__ ei32,
                          int* __restrict__ src, int* __restrict__ dst) {
    int e = blockIdx.x * blockDim.x + threadIdx.x;
    if (e >= NE) return;
    int is64 = g_eflag[0];
    int s, d;
    if (is64) { s = ei32[2 * e]; d = ei32[2 * (NE + e)]; }
    else      { s = ei32[e];     d = ei32[NE + e]; }
    s = min(max(s, 0), NN - 1);
    d = min(max(d, 0), NN - 1);
    src[e] = s;
    dst[e] = d;
}

// ---------------- CSR build ----------------
__global__ void k_fill_i(int* p, int n, int v) {
    int i = blockIdx.x * blockDim.x + threadIdx.x;
    if (i < n) p[i] = v;
}
__global__ void k_count(const int* __restrict__ dst, int* __restrict__ cnt) {
    int e = blockIdx.x * blockDim.x + threadIdx.x;
    if (e < NE) atomicAdd(&cnt[dst[e]], 1);
}
__global__ void k_dinv(const int* __restrict__ cnt, float* __restrict__ dinv) {
    int i = blockIdx.x * blockDim.x + threadIdx.x;
    if (i < NN) dinv[i] = rsqrtf((float)cnt[i]);
}
__global__ void scan1(const int* __restrict__ cnt, int* __restrict__ bsum) {
    __shared__ int sh[SCAN_BS];
    int i = blockIdx.x * SCAN_BS + threadIdx.x;
    sh[threadIdx.x] = (i < NN) ? cnt[i] : 0;
    __syncthreads();
    for (int s = SCAN_BS / 2; s; s >>= 1) {
        if (threadIdx.x < s) sh[threadIdx.x] += sh[threadIdx.x + s];
        __syncthreads();
    }
    if (threadIdx.x == 0) bsum[blockIdx.x] = sh[0];
}
__global__ void scan2(int* __restrict__ bsum) {
    __shared__ int sh[1024];
    int v = (threadIdx.x < SCAN_NB) ? bsum[threadIdx.x] : 0;
    sh[threadIdx.x] = v;
    __syncthreads();
    for (int o = 1; o < 1024; o <<= 1) {
        int t = (threadIdx.x >= o) ? sh[threadIdx.x - o] : 0;
        __syncthreads();
        sh[threadIdx.x] += t;
        __syncthreads();
    }
    if (threadIdx.x < SCAN_NB) bsum[threadIdx.x] = sh[threadIdx.x] - v;
}
__global__ void scan3(const int* __restrict__ cnt, const int* __restrict__ bsum,
                      int* __restrict__ off) {
    __shared__ int sh[SCAN_BS];
    int i = blockIdx.x * SCAN_BS + threadIdx.x;
    int v = (i < NN) ? cnt[i] : 0;
    sh[threadIdx.x] = v;
    __syncthreads();
    for (int o = 1; o < SCAN_BS; o <<= 1) {
        int t = (threadIdx.x >= o) ? sh[threadIdx.x - o] : 0;
        __syncthreads();
        sh[threadIdx.x] += t;
        __syncthreads();
    }
    if (i <= NN) off[i] = bsum[blockIdx.x] + sh[threadIdx.x] - v;
}
__global__ void k_copy_i(const int* __restrict__ a, int* __restrict__ b, int n) {
    int i = blockIdx.x * blockDim.x + threadIdx.x;
    if (i < n) b[i] = a[i];
}
__global__ void k_bucket(const int* __restrict__ src, const int* __restrict__ dst,
                         const float* __restrict__ dinv, int* __restrict__ cur,
                         int* __restrict__ cs, float* __restrict__ cw) {
    int t = blockIdx.x * blockDim.x + threadIdx.x;
    if (t >= NE2) return;
    int s, d;
    if (t < NE) { s = src[t]; d = dst[t]; }
    else        { s = d = t - NE; }
    int pos = atomicAdd(&cur[d], 1);
    cs[pos] = s;
    cw[pos] = dinv[s] * dinv[d];
}

// ---------------- GEMM: C[n,k] = A[n,m] @ W[m,k] ----------------
// EPI: 0 = none, 1 = GCN2 (relu((1-b)A + b*AW), m==k), 2 = relu(AW + bias)
#define TM 128
#define TN 128
#define TK 16
#define LDP 132
template <int EPI>
__global__ __launch_bounds__(256) void gemm_k(
    const float* __restrict__ A, const float* __restrict__ W,
    float* __restrict__ C, int n, int m, int k, float beta,
    const float* __restrict__ bias) {
    __shared__ float As[2][TK][LDP];
    __shared__ float Ws[2][TK][LDP];
    const int tid  = threadIdx.x;
    const int row0 = blockIdx.y * TM;
    const int col0 = blockIdx.x * TN;
    const int ty = tid >> 4, tx = tid & 15;
    const int ry = ty * 8, rx = tx * 8;

    const int a_r0  = (tid * 2) >> 2,        a_r1  = (tid * 2 + 1) >> 2;
    const int a_kq0 = ((tid * 2) & 3) * 4,   a_kq1 = ((tid * 2 + 1) & 3) * 4;
    const int w_kk0 = (tid * 2) >> 5,        w_kk1 = (tid * 2 + 1) >> 5;
    const int w_cq0 = ((tid * 2) & 31) * 4,  w_cq1 = ((tid * 2 + 1) & 31) * 4;

    float acc[8][8];
    #pragma unroll
    for (int i = 0; i < 8; i++)
        #pragma unroll
        for (int j = 0; j < 8; j++) acc[i][j] = 0.0f;

    float4 pa0, pa1, pw0, pw1;
    const float4 Z = make_float4(0.f, 0.f, 0.f, 0.f);

    {
        int gr0 = row0 + a_r0, gr1 = row0 + a_r1;
        pa0 = (gr0 < n && a_kq0 < m) ? *(const float4*)&A[(size_t)gr0 * m + a_kq0] : Z;
        pa1 = (gr1 < n && a_kq1 < m) ? *(const float4*)&A[(size_t)gr1 * m + a_kq1] : Z;
        int gc0 = col0 + w_cq0, gc1 = col0 + w_cq1;
        pw0 = (w_kk0 < m && gc0 < k) ? *(const float4*)&W[(size_t)w_kk0 * k + gc0] : Z;
        pw1 = (w_kk1 < m && gc1 < k) ? *(const float4*)&W[(size_t)w_kk1 * k + gc1] : Z;
        As[0][a_kq0 + 0][a_r0] = pa0.x; As[0][a_kq0 + 1][a_r0] = pa0.y;
        As[0][a_kq0 + 2][a_r0] = pa0.z; As[0][a_kq0 + 3][a_r0] = pa0.w;
        As[0][a_kq1 + 0][a_r1] = pa1.x; As[0][a_kq1 + 1][a_r1] = pa1.y;
        As[0][a_kq1 + 2][a_r1] = pa1.z; As[0][a_kq1 + 3][a_r1] = pa1.w;
        *(float4*)&Ws[0][w_kk0][w_cq0] = pw0;
        *(float4*)&Ws[0][w_kk1][w_cq1] = pw1;
        __syncthreads();
    }

    const int nt = (m + TK - 1) / TK;
    for (int t = 0; t < nt; t++) {
        const int buf = t & 1;
        if (t + 1 < nt) {
            int mb = (t + 1) * TK;
            int gr0 = row0 + a_r0, gr1 = row0 + a_r1;
            int gk0 = mb + a_kq0,  gk1 = mb + a_kq1;
            pa0 = (gr0 < n && gk0 < m) ? *(const float4*)&A[(size_t)gr0 * m + gk0] : Z;
            pa1 = (gr1 < n && gk1 < m) ? *(const float4*)&A[(size_t)gr1 * m + gk1] : Z;
            int wk0 = mb + w_kk0, wk1 = mb + w_kk1;
            int gc0 = col0 + w_cq0, gc1 = col0 + w_cq1;
            pw0 = (wk0 < m && gc0 < k) ? *(const float4*)&W[(size_t)wk0 * k + gc0] : Z;
            pw1 = (wk1 < m && gc1 < k) ? *(const float4*)&W[(size_t)wk1 * k + gc1] : Z;
        }
        #pragma unroll
        for (int kk = 0; kk < TK; kk++) {
            float4 a0 = *(const float4*)&As[buf][kk][ry];
            float4 a1 = *(const float4*)&As[buf][kk][ry + 4];
            float4 b0 = *(const float4*)&Ws[buf][kk][rx];
            float4 b1 = *(const float4*)&Ws[buf][kk][rx + 4];
            float a[8] = {a0.x, a0.y, a0.z, a0.w, a1.x, a1.y, a1.z, a1.w};
            float b[8] = {b0.x, b0.y, b0.z, b0.w, b1.x, b1.y, b1.z, b1.w};
            #pragma unroll
            for (int i = 0; i < 8; i++)
                #pragma unroll
                for (int j = 0; j < 8; j++) acc[i][j] += a[i] * b[j];
        }
        if (t + 1 < nt) {
            const int nb = buf ^ 1;
            As[nb][a_kq0 + 0][a_r0] = pa0.x; As[nb][a_kq0 + 1][a_r0] = pa0.y;
            As[nb][a_kq0 + 2][a_r0] = pa0.z; As[nb][a_kq0 + 3][a_r0] = pa0.w;
            As[nb][a_kq1 + 0][a_r1] = pa1.x; As[nb][a_kq1 + 1][a_r1] = pa1.y;
            As[nb][a_kq1 + 2][a_r1] = pa1.z; As[nb][a_kq1 + 3][a_r1] = pa1.w;
            *(float4*)&Ws[nb][w_kk0][w_cq0] = pw0;
            *(float4*)&Ws[nb][w_kk1][w_cq1] = pw1;
            __syncthreads();
        }
    }

    #pragma unroll
    for (int i = 0; i < 8; i++) {
        int gr = row0 + ry + i;
        if (gr >= n) continue;
        #pragma unroll
        for (int jq = 0; jq < 2; jq++) {
            int gc = col0 + rx + jq * 4;
            if (gc >= k) continue;
            float4 v = make_float4(acc[i][jq * 4], acc[i][jq * 4 + 1],
                                   acc[i][jq * 4 + 2], acc[i][jq * 4 + 3]);
            if (EPI == 1) {
                float4 x0 = *(const float4*)&A[(size_t)gr * m + gc];
                v.x = fmaxf(beta * v.x + (1.0f - beta) * x0.x, 0.f);
                v.y = fmaxf(beta * v.y + (1.0f - beta) * x0.y, 0.f);
                v.z = fmaxf(beta * v.z + (1.0f - beta) * x0.z, 0.f);
                v.w = fmaxf(beta * v.w + (1.0f - beta) * x0.w, 0.f);
            } else if (EPI == 2) {
                float4 b = *(const float4*)&bias[gc];
                v.x = fmaxf(v.x + b.x, 0.f); v.y = fmaxf(v.y + b.y, 0.f);
                v.z = fmaxf(v.z + b.z, 0.f); v.w = fmaxf(v.w + b.w, 0.f);
            }
            *(float4*)&C[(size_t)gr * k + gc] = v;
        }
    }
}

// ---------------- pull-based GCN propagation (CSR, no atomics) ----------------
// MODE 0: relu(acc+bias)  MODE 1: 0.5*(acc+x0)  MODE 2: acc+bias  MODE 3: acc
template <int D4, int MODE>
__global__ void prop_pull(const float4* __restrict__ h, float4* __restrict__ o,
                          const float* __restrict__ aux,
                          const int* __restrict__ off, const int* __restrict__ csr_s,
                          const float* __restrict__ csr_w) {
    constexpr int TPN = (D4 < 32) ? D4 : 32;
    constexpr int NPW = 32 / TPN;
    constexpr int R   = D4 / TPN;
    int gwarp = (blockIdx.x * blockDim.x + threadIdx.x) >> 5;
    int lane  = threadIdx.x & 31;
    int node  = gwarp * NPW + lane / TPN;
    int tl    = lane % TPN;
    if (node >= NN) return;

    float4 acc[R];
    #pragma unroll
    for (int r = 0; r < R; r++) acc[r] = make_float4(0.f, 0.f, 0.f, 0.f);

    int j0 = off[node], j1 = off[node + 1];
    int j = j0;
    for (; j + 1 < j1; j += 2) {
        int   s0 = csr_s[j],     s1 = csr_s[j + 1];
        float w0 = csr_w[j],     w1 = csr_w[j + 1];
        #pragma unroll
        for (int r = 0; r < R; r++) {
            float4 v0 = h[(size_t)s0 * D4 + tl + r * TPN];
            float4 v1 = h[(size_t)s1 * D4 + tl + r * TPN];
            acc[r].x += w0 * v0.x + w1 * v1.x;
            acc[r].y += w0 * v0.y + w1 * v1.y;
            acc[r].z += w0 * v0.z + w1 * v1.z;
            acc[r].w += w0 * v0.w + w1 * v1.w;
        }
    }
    if (j < j1) {
        int s0 = csr_s[j];
        float w0 = csr_w[j];
        #pragma unroll
        for (int r = 0; r < R; r++) {
            float4 v0 = h[(size_t)s0 * D4 + tl + r * TPN];
            acc[r].x += w0 * v0.x; acc[r].y += w0 * v0.y;
            acc[r].z += w0 * v0.z; acc[r].w += w0 * v0.w;
        }
    }

    const float4* aux4 = (const float4*)aux;
    #pragma unroll
    for (int r = 0; r < R; r++) {
        int c = tl + r * TPN;
        float4 v = acc[r];
        if (MODE == 0 || MODE == 2) {
            float4 b = aux4[c];
            v.x += b.x; v.y += b.y; v.z += b.z; v.w += b.w;
            if (MODE == 0) {
                v.x = fmaxf(v.x, 0.f); v.y = fmaxf(v.y, 0.f);
                v.z = fmaxf(v.z, 0.f); v.w = fmaxf(v.w, 0.f);
            }
        } else if (MODE == 1) {
            float4 x0 = aux4[(size_t)node * D4 + c];
            v.x = 0.5f * (v.x + x0.x); v.y = 0.5f * (v.y + x0.y);
            v.z = 0.5f * (v.z + x0.z); v.w = 0.5f * (v.w + x0.w);
        }
        o[(size_t)node * D4 + c] = v;
    }
}

// ---------------- GATv2 (node-parallel, online softmax) ----------------
// one warp per dst node: preload xr[d]+att in regs, loop CSR slice computing
// logits (write ea), running max + rescaled exp-sum (flash-softmax).
__global__ void gat_logit(const float* __restrict__ xl, const float* __restrict__ xr,
                          const int* __restrict__ off, const int* __restrict__ cs,
                          const float* __restrict__ att, float* __restrict__ ea,
                          float4* __restrict__ amax4, float4* __restrict__ asum4) {
    int node = (blockIdx.x * blockDim.x + threadIdx.x) >> 5;
    int lane = threadIdx.x & 31;
    if (node >= NN) return;
    int j0 = off[node], j1 = off[node + 1];

    float xrh[4], atth[4];
    #pragma unroll
    for (int h = 0; h < 4; h++) {
        xrh[h]  = xr[(size_t)node * 128 + h * 32 + lane];
        atth[h] = att[h * 32 + lane];
    }

    float mx[4] = {-1e30f, -1e30f, -1e30f, -1e30f};
    float sm[4] = {0.f, 0.f, 0.f, 0.f};

    for (int j = j0; j < j1; j++) {
        int s = cs[j];
        const float* ls = xl + (size_t)s * 128;
        float a[4];
        #pragma unroll
        for (int h = 0; h < 4; h++) {
            float v = ls[h * 32 + lane] + xrh[h];
            v = (v > 0.0f) ? v : 0.2f * v;
            v *= atth[h];
            #pragma unroll
            for (int o = 16; o; o >>= 1) v += __shfl_xor_sync(0xffffffffu, v, o);
            a[h] = v;
            float nm = fmaxf(mx[h], v);
            sm[h] = sm[h] * __expf(mx[h] - nm) + __expf(v - nm);
            mx[h] = nm;
        }
        if (lane == 0)
            reinterpret_cast<float4*>(ea)[j] = make_float4(a[0], a[1], a[2], a[3]);
    }
    if (lane == 0) {
        amax4[node] = make_float4(mx[0], mx[1], mx[2], mx[3]);
        asum4[node] = make_float4(sm[0], sm[1], sm[2], sm[3]);
    }
}

// one warp per node: weighted gather with precomputed amax/asum, + bias + relu
__global__ void gat_gather(const float* __restrict__ ea, const float4* __restrict__ xl,
                           const int* __restrict__ off, const int* __restrict__ cs,
                           const float4* __restrict__ amax4, const float4* __restrict__ asum4,
                           const float* __restrict__ bg, float4* __restrict__ out) {
    int node = (blockIdx.x * blockDim.x + threadIdx.x) >> 5;
    int lane = threadIdx.x & 31;
    if (node >= NN) return;
    int j0 = off[node], j1 = off[node + 1];

    int h = lane >> 3;
    float4 mxv = amax4[node], smv = asum4[node];
    float mxh = (h == 0) ? mxv.x : (h == 1) ? mxv.y : (h == 2) ? mxv.z : mxv.w;
    float smh = (h == 0) ? smv.x : (h == 1) ? smv.y : (h == 2) ? smv.z : smv.w;
    float inv = 1.0f / (smh + 1e-16f);

    float4 acc = ((const float4*)bg)[lane];
    for (int j = j0; j < j1; j++) {
        int s = cs[j];
        float p = __expf(ea[(size_t)j * 4 + h] - mxh) * inv;
        float4 v = xl[(size_t)s * 32 + lane];
        acc.x += p * v.x; acc.y += p * v.y; acc.z += p * v.z; acc.w += p * v.w;
    }
    acc.x = fmaxf(acc.x, 0.f); acc.y = fmaxf(acc.y, 0.f);
    acc.z = fmaxf(acc.z, 0.f); acc.w = fmaxf(acc.w, 0.f);
    out[(size_t)node * 32 + lane] = acc;
}

// ---------------- host-side helpers ----------------
static void gemm(const float* A, const float* W, float* C, int n, int m, int k,
                 int epi, float beta, const float* bias, cudaStream_t st) {
    dim3 grid(divup(k, TN), divup(n, TM));
    if (epi == 1)      gemm_k<1><<<grid, 256, 0, st>>>(A, W, C, n, m, k, beta, nullptr);
    else if (epi == 2) gemm_k<2><<<grid, 256, 0, st>>>(A, W, C, n, m, k, 0.0f, bias);
    else               gemm_k<0><<<grid, 256, 0, st>>>(A, W, C, n, m, k, 0.0f, nullptr);
}

template <int D4, int MODE>
static void prop_launch(const float* h, float* o, const float* aux,
                        const int* off, const int* cs, const float* cw) {
    constexpr int NPW = (D4 < 32) ? (32 / D4) : 1;
    int warps = divup(NN, NPW);
    prop_pull<D4, MODE><<<divup((long long)warps * 32, 256), 256>>>(
        (const float4*)h, (float4*)o, aux, off, cs, cw);
}

static cudaStream_t s_side = nullptr;
static cudaEvent_t  s_ev0, s_ev1, s_ev2, s_ev3;

extern "C" void kernel_launch(void* const* d_in, const int* in_sizes, int n_in,
                              void* d_out, int out_size) {
    if (!s_side) {
        cudaStreamCreateWithFlags(&s_side, cudaStreamNonBlocking);
        cudaEventCreateWithFlags(&s_ev0, cudaEventDisableTiming);
        cudaEventCreateWithFlags(&s_ev1, cudaEventDisableTiming);
        cudaEventCreateWithFlags(&s_ev2, cudaEventDisableTiming);
        cudaEventCreateWithFlags(&s_ev3, cudaEventDisableTiming);
    }
    const cudaStream_t MAIN = 0;

    const float* x   = (const float*)d_in[0];
    const int*   ei32= (const int*)d_in[1];
    const float* W1 = (const float*)d_in[2];  const float* b1 = (const float*)d_in[3];
    const float* W2 = (const float*)d_in[4];  const float* b2 = (const float*)d_in[5];
    const float* W3 = (const float*)d_in[6];  const float* b3 = (const float*)d_in[7];
    const float* W4 = (const float*)d_in[8];  const float* b4 = (const float*)d_in[9];
    const float* Wl = (const float*)d_in[10]; const float* Wr = (const float*)d_in[11];
    const float* att= (const float*)d_in[12]; const float* bg = (const float*)d_in[13];
    const float* Wc1= (const float*)d_in[14];
    const float* W5 = (const float*)d_in[15]; const float* b5 = (const float*)d_in[16];
    const float* Wc2= (const float*)d_in[17];
    const float* Wo = (const float*)d_in[18]; const float* bo = (const float*)d_in[19];
    float* out = (float*)d_out;

    float *x1, *x2, *A, *B, *C, *D, *ea, *amax, *asum, *dinv, *cw;
    int *src, *dst, *cnt, *off, *cur, *bsum, *cs;
    cudaGetSymbolAddress((void**)&x1,   g_x1);
    cudaGetSymbolAddress((void**)&x2,   g_x2);
    cudaGetSymbolAddress((void**)&A,    g_A);
    cudaGetSymbolAddress((void**)&B,    g_B);
    cudaGetSymbolAddress((void**)&C,    g_C);
    cudaGetSymbolAddress((void**)&D,    g_D);
    cudaGetSymbolAddress((void**)&ea,   g_ea);
    cudaGetSymbolAddress((void**)&amax, g_amax);
    cudaGetSymbolAddress((void**)&asum, g_asum);
    cudaGetSymbolAddress((void**)&dinv, g_dinv);
    cudaGetSymbolAddress((void**)&src,  g_src);
    cudaGetSymbolAddress((void**)&dst,  g_dst);
    cudaGetSymbolAddress((void**)&cnt,  g_cnt);
    cudaGetSymbolAddress((void**)&off,  g_off);
    cudaGetSymbolAddress((void**)&cur,  g_cur);
    cudaGetSymbolAddress((void**)&bsum, g_bsum);
    cudaGetSymbolAddress((void**)&cs,   g_csr_s);
    cudaGetSymbolAddress((void**)&cw,   g_csr_w);

    const float BETA = logf(1.05f);

    // ---- head: detect/convert on MAIN, then fork CSR build to side stream ----
    k_detect<<<1, 256>>>(ei32);                               // #1
    k_convert<<<divup(NE, 256), 256>>>(ei32, src, dst);       // #2
    cudaEventRecord(s_ev0, MAIN);
    cudaStreamWaitEvent(s_side, s_ev0, 0);

    k_fill_i<<<divup(NN, 256), 256, 0, s_side>>>(cnt, NN, 1);             // #3
    gemm(x, W1, A, NN, 300, 256, 0, 0.0f, nullptr, MAIN);                  // #4 <- profiled
    k_count<<<divup(NE, 256), 256, 0, s_side>>>(dst, cnt);
    k_dinv<<<divup(NN, 256), 256, 0, s_side>>>(cnt, dinv);
    scan1<<<SCAN_NB, SCAN_BS, 0, s_side>>>(cnt, bsum);
    scan2<<<1, 1024, 0, s_side>>>(bsum);
    scan3<<<SCAN_NB, SCAN_BS, 0, s_side>>>(cnt, bsum, off);
    k_copy_i<<<divup(NN, 256), 256, 0, s_side>>>(off, cur, NN);
    k_bucket<<<divup(NE2, 256), 256, 0, s_side>>>(src, dst, dinv, cur, cs, cw);
    cudaEventRecord(s_ev1, s_side);
    cudaStreamWaitEvent(MAIN, s_ev1, 0);   // join: CSR + gemm1 both done

    // ---- x1 = relu(prop(x@W1)+b1) ----
    prop_launch<64, 0>(A, x1, b1, off, cs, cw);

    // ---- x2 = relu(prop(x1@W2)+b2) ----
    gemm(x1, W2, A, NN, 256, 128, 0, 0.0f, nullptr, MAIN);
    prop_launch<32, 0>(A, x2, b2, off, cs, cw);

    // ---- x3 = relu(prop(x2@W3)+b3)  (64) ----
    gemm(x2, W3, A, NN, 128, 64, 0, 0.0f, nullptr, MAIN);
    prop_launch<16, 0>(A, B, b3, off, cs, cw);

    // ---- x3 = relu(prop(x3@W4)+b4)  (32) ----
    gemm(B, W4, A, NN, 64, 32, 0, 0.0f, nullptr, MAIN);
    prop_launch<8, 0>(A, B, b4, off, cs, cw);

    // ---- GATv2 (128); xl=C (main), xr=A (side, overlapped) ----
    cudaEventRecord(s_ev2, MAIN);
    cudaStreamWaitEvent(s_side, s_ev2, 0);
    gemm(B, Wr, A, NN, 32, 128, 0, 0.0f, nullptr, s_side);
    cudaEventRecord(s_ev3, s_side);
    gemm(B, Wl, C, NN, 32, 128, 0, 0.0f, nullptr, MAIN);
    cudaStreamWaitEvent(MAIN, s_ev3, 0);
    gat_logit<<<divup((long long)NN * 32, 256), 256>>>(C, A, off, cs, att, ea,
                                                       (float4*)amax, (float4*)asum);
    gat_gather<<<divup((long long)NN * 32, 256), 256>>>(ea, (const float4*)C, off, cs,
                                                        (const float4*)amax,
                                                        (const float4*)asum, bg, (float4*)D);

    // ---- GCN2 #1 with x0=x2 (128) ----
    prop_launch<32, 1>(D, A, x2, off, cs, cw);
    gemm(A, Wc1, B, NN, 128, 128, 1, BETA, nullptr, MAIN);

    // ---- x3 = relu(prop(B)@W5 + b5)  (prop commuted to 128-d) ----
    prop_launch<32, 3>(B, A, nullptr, off, cs, cw);
    gemm(A, W5, C, NN, 128, 256, 2, 0.0f, b5, MAIN);

    // ---- GCN2 #2 with x0=x1 (256) ----
    prop_launch<64, 1>(C, A, x1, off, cs, cw);
    gemm(A, Wc2, B, NN, 256, 256, 1, BETA, nullptr, MAIN);

    // ---- out = prop(x3@Wo) + bo ----
    gemm(B, Wo, A, NN, 256, 128, 0, 0.0f, nullptr, MAIN);
    prop_launch<32, 2>(A, out, bo, off, cs, cw);
}

// round 10
// speedup vs baseline: 2.9178x; 1.5442x over previous
#include <cuda_runtime.h>
#include <cuda_bf16.h>
#include <cstdint>
#include <math.h>

#define NN 50000
#define NE 800000
#define NE2 850000
#define SCAN_BS 512
#define SCAN_NB ((NN + SCAN_BS - 1) / SCAN_BS)

// ---------------- device scratch ----------------
__device__ __align__(16) float g_x1[(size_t)NN * 256];
__device__ __align__(16) float g_x2[(size_t)NN * 128];
__device__ __align__(16) float g_A [(size_t)NN * 256];
__device__ __align__(16) float g_B [(size_t)NN * 256];
__device__ __align__(16) float g_C [(size_t)NN * 256];
__device__ __align__(16) float g_D [(size_t)NN * 128];
__device__ __align__(16) float g_ea[(size_t)NE2 * 4];
__device__ __align__(16) float g_amax[(size_t)NN * 4];
__device__ __align__(16) float g_asum[(size_t)NN * 4];
__device__ float    g_dinv[NN];
__device__ int      g_src[NE];
__device__ int      g_dst[NE];
__device__ int      g_cnt[NN];
__device__ int      g_off[NN + 1];
__device__ int      g_cur[NN];
__device__ int      g_bsum[SCAN_NB + 32];
__device__ int      g_csr_s[NE2];
__device__ float    g_csr_w[NE2];
__device__ int      g_eflag[1];
// split-bf16 transposed weights: [k][mpad] K-major, hi plane then lo plane
__device__ __align__(16) __nv_bfloat16 g_wt[600000];

static inline int divup(long long a, int b) { return (int)((a + b - 1) / b); }

// ---------------- PTX helpers (plain-sm_100 legal) ----------------
__device__ __forceinline__ uint32_t smem_u32(const void* p) {
    uint32_t a;
    asm("{ .reg .u64 t; cvta.to.shared.u64 t, %1; cvt.u32.u64 %0, t; }" : "=r"(a) : "l"(p));
    return a;
}
__device__ __forceinline__ void ldm_x4(uint32_t (&r)[4], uint32_t addr) {
    asm volatile("ldmatrix.sync.aligned.m8n8.x4.shared.b16 {%0,%1,%2,%3}, [%4];"
                 : "=r"(r[0]), "=r"(r[1]), "=r"(r[2]), "=r"(r[3]) : "r"(addr));
}
__device__ __forceinline__ void mma16816(float (&d)[4], const uint32_t (&a)[4],
                                         uint32_t b0, uint32_t b1) {
    asm volatile(
        "mma.sync.aligned.m16n8k16.row.col.f32.bf16.bf16.f32 "
        "{%0,%1,%2,%3}, {%4,%5,%6,%7}, {%8,%9}, {%0,%1,%2,%3};"
        : "+f"(d[0]), "+f"(d[1]), "+f"(d[2]), "+f"(d[3])
        : "r"(a[0]), "r"(a[1]), "r"(a[2]), "r"(a[3]), "r"(b0), "r"(b1));
}

// ---------------- edge-index dtype detection + conversion ----------------
__global__ void k_detect(const int* __restrict__ ei32) {
    __shared__ int cnt;
    if (threadIdx.x == 0) cnt = 0;
    __syncthreads();
    int nz = 0;
    for (int i = threadIdx.x; i < 2048; i += blockDim.x)
        if (ei32[2 * i + 1] != 0) nz++;
    atomicAdd(&cnt, nz);
    __syncthreads();
    if (threadIdx.x == 0) g_eflag[0] = (cnt == 0) ? 1 : 0;
}
__global__ void k_convert(const int* __restrict__ ei32,
                          int* __restrict__ src, int* __restrict__ dst) {
    int e = blockIdx.x * blockDim.x + threadIdx.x;
    if (e >= NE) return;
    int is64 = g_eflag[0];
    int s, d;
    if (is64) { s = ei32[2 * e]; d = ei32[2 * (NE + e)]; }
    else      { s = ei32[e];     d = ei32[NE + e]; }
    s = min(max(s, 0), NN - 1);
    d = min(max(d, 0), NN - 1);
    src[e] = s; dst[e] = d;
}

// ---------------- weight pre-transpose + bf16 split ----------------
__global__ void k_splitw(const float* __restrict__ W, __nv_bfloat16* __restrict__ wt,
                         int m, int k, int mpad) {
    int idx = blockIdx.x * blockDim.x + threadIdx.x;
    int tot = k * mpad;
    if (idx >= tot) return;
    int j = idx / mpad, kk = idx % mpad;
    float f = (kk < m) ? W[(size_t)kk * k + j] : 0.0f;
    __nv_bfloat16 h = __float2bfloat16(f);
    __nv_bfloat16 l = __float2bfloat16(f - __bfloat162float(h));
    wt[idx] = h;
    wt[tot + idx] = l;
}

// ---------------- CSR build ----------------
__global__ void k_fill_i(int* p, int n, int v) {
    int i = blockIdx.x * blockDim.x + threadIdx.x;
    if (i < n) p[i] = v;
}
__global__ void k_count(const int* __restrict__ dst, int* __restrict__ cnt) {
    int e = blockIdx.x * blockDim.x + threadIdx.x;
    if (e < NE) atomicAdd(&cnt[dst[e]], 1);
}
__global__ void k_dinv(const int* __restrict__ cnt, float* __restrict__ dinv) {
    int i = blockIdx.x * blockDim.x + threadIdx.x;
    if (i < NN) dinv[i] = rsqrtf((float)cnt[i]);
}
__global__ void scan1(const int* __restrict__ cnt, int* __restrict__ bsum) {
    __shared__ int sh[SCAN_BS];
    int i = blockIdx.x * SCAN_BS + threadIdx.x;
    sh[threadIdx.x] = (i < NN) ? cnt[i] : 0;
    __syncthreads();
    for (int s = SCAN_BS / 2; s; s >>= 1) {
        if (threadIdx.x < s) sh[threadIdx.x] += sh[threadIdx.x + s];
        __syncthreads();
    }
    if (threadIdx.x == 0) bsum[blockIdx.x] = sh[0];
}
__global__ void scan2(int* __restrict__ bsum) {
    __shared__ int sh[1024];
    int v = (threadIdx.x < SCAN_NB) ? bsum[threadIdx.x] : 0;
    sh[threadIdx.x] = v;
    __syncthreads();
    for (int o = 1; o < 1024; o <<= 1) {
        int t = (threadIdx.x >= o) ? sh[threadIdx.x - o] : 0;
        __syncthreads();
        sh[threadIdx.x] += t;
        __syncthreads();
    }
    if (threadIdx.x < SCAN_NB) bsum[threadIdx.x] = sh[threadIdx.x] - v;
}
__global__ void scan3(const int* __restrict__ cnt, const int* __restrict__ bsum,
                      int* __restrict__ off) {
    __shared__ int sh[SCAN_BS];
    int i = blockIdx.x * SCAN_BS + threadIdx.x;
    int v = (i < NN) ? cnt[i] : 0;
    sh[threadIdx.x] = v;
    __syncthreads();
    for (int o = 1; o < SCAN_BS; o <<= 1) {
        int t = (threadIdx.x >= o) ? sh[threadIdx.x - o] : 0;
        __syncthreads();
        sh[threadIdx.x] += t;
        __syncthreads();
    }
    if (i <= NN) off[i] = bsum[blockIdx.x] + sh[threadIdx.x] - v;
}
__global__ void k_copy_i(const int* __restrict__ a, int* __restrict__ b, int n) {
    int i = blockIdx.x * blockDim.x + threadIdx.x;
    if (i < n) b[i] = a[i];
}
__global__ void k_bucket(const int* __restrict__ src, const int* __restrict__ dst,
                         const float* __restrict__ dinv, int* __restrict__ cur,
                         int* __restrict__ cs, float* __restrict__ cw) {
    int t = blockIdx.x * blockDim.x + threadIdx.x;
    if (t >= NE2) return;
    int s, d;
    if (t < NE) { s = src[t]; d = dst[t]; }
    else        { s = d = t - NE; }
    int pos = atomicAdd(&cur[d], 1);
    cs[pos] = s;
    cw[pos] = dinv[s] * dinv[d];
}

// ---------------- mma.sync bf16x3 GEMM: C[n,k] = A[n,m] @ W[m,k] ----------------
// Block 128x128, 8 warps (4 M x 2 N), warp tile 32x64, K-tile 32 (2 x k16).
// EPI: 0 none, 1 GCN2 relu((1-b)A + b*AW) (m==k), 2 relu(AW + bias)
#define LDS_B 80
template <int EPI>
__global__ __launch_bounds__(256) void gemm_mma(
    const float* __restrict__ A, const __nv_bfloat16* __restrict__ Wt,
    float* __restrict__ C, int n, int m, int k, int mpad, float beta,
    const float* __restrict__ bias) {
    __shared__ __align__(16) char sAh[128 * LDS_B];
    __shared__ __align__(16) char sAl[128 * LDS_B];
    __shared__ __align__(16) char sBh[128 * LDS_B];
    __shared__ __align__(16) char sBl[128 * LDS_B];

    const int tid  = threadIdx.x;
    const int wid  = tid >> 5, lane = tid & 31;
    const int warp_m = wid & 3, warp_n = wid >> 2;
    const int row0 = blockIdx.y * 128;
    const int col0 = blockIdx.x * 128;
    const int planeoff = k * mpad;

    const uint32_t ah_b = smem_u32(sAh), al_b = smem_u32(sAl);
    const uint32_t bh_b = smem_u32(sBh), bl_b = smem_u32(sBl);
    const int lr = lane & 15, lc = lane >> 4;
    const uint32_t a_off = (uint32_t)(warp_m * 32 + lr) * LDS_B + lc * 16;
    const uint32_t b_off = (uint32_t)(warp_n * 64 + lr) * LDS_B + lc * 16;

    float acc[2][8][4];
    #pragma unroll
    for (int i = 0; i < 2; i++)
        #pragma unroll
        for (int j = 0; j < 8; j++)
            #pragma unroll
            for (int r = 0; r < 4; r++) acc[i][j][r] = 0.0f;

    const uint4 Z4 = make_uint4(0, 0, 0, 0);

    for (int kt = 0; kt < mpad; kt += 32) {
        __syncthreads();
        // ---- A tile: 128 x 32 fp32 -> bf16 hi/lo ----
        #pragma unroll
        for (int i = 0; i < 4; i++) {
            int idx = tid + i * 256;
            int r = idx >> 3, q = idx & 7;
            int gr = row0 + r, gk = kt + q * 4;
            float4 v = make_float4(0.f, 0.f, 0.f, 0.f);
            if (gr < n && gk < m) v = *(const float4*)&A[(size_t)gr * m + gk];
            __nv_bfloat16 h0 = __float2bfloat16(v.x), h1 = __float2bfloat16(v.y);
            __nv_bfloat16 h2 = __float2bfloat16(v.z), h3 = __float2bfloat16(v.w);
            __nv_bfloat16 l0 = __float2bfloat16(v.x - __bfloat162float(h0));
            __nv_bfloat16 l1 = __float2bfloat16(v.y - __bfloat162float(h1));
            __nv_bfloat16 l2 = __float2bfloat16(v.z - __bfloat162float(h2));
            __nv_bfloat16 l3 = __float2bfloat16(v.w - __bfloat162float(h3));
            __nv_bfloat162 hp0 = {h0, h1}, hp1 = {h2, h3};
            __nv_bfloat162 lp0 = {l0, l1}, lp1 = {l2, l3};
            uint2 uh = make_uint2(*(uint32_t*)&hp0, *(uint32_t*)&hp1);
            uint2 ul = make_uint2(*(uint32_t*)&lp0, *(uint32_t*)&lp1);
            *(uint2*)(sAh + r * LDS_B + q * 8) = uh;
            *(uint2*)(sAl + r * LDS_B + q * 8) = ul;
        }
        // ---- B tile: 128 n-rows x 32 k bf16 (pre-split) ----
        #pragma unroll
        for (int i = 0; i < 2; i++) {
            int idx = tid + i * 256;
            int j = idx >> 2, kq = idx & 3;
            int gj = col0 + j;
            uint4 vh = Z4, vl = Z4;
            if (gj < k) {
                size_t g = (size_t)gj * mpad + kt + kq * 8;
                vh = *(const uint4*)&Wt[g];
                vl = *(const uint4*)&Wt[planeoff + g];
            }
            *(uint4*)(sBh + j * LDS_B + kq * 16) = vh;
            *(uint4*)(sBl + j * LDS_B + kq * 16) = vl;
        }
        __syncthreads();

        #pragma unroll
        for (int ks = 0; ks < 2; ks++) {
            const uint32_t kb2 = ks * 32;
            uint32_t ah[2][4], al[2][4], bh[4][4], bl[4][4];
            #pragma unroll
            for (int mt = 0; mt < 2; mt++) {
                ldm_x4(ah[mt], ah_b + a_off + mt * (16 * LDS_B) + kb2);
                ldm_x4(al[mt], al_b + a_off + mt * (16 * LDS_B) + kb2);
            }
            #pragma unroll
            for (int nt = 0; nt < 4; nt++) {
                ldm_x4(bh[nt], bh_b + b_off + nt * (16 * LDS_B) + kb2);
                ldm_x4(bl[nt], bl_b + b_off + nt * (16 * LDS_B) + kb2);
            }
            #pragma unroll
            for (int mt = 0; mt < 2; mt++)
                #pragma unroll
                for (int nt = 0; nt < 4; nt++) {
                    mma16816(acc[mt][nt*2+0], ah[mt], bh[nt][0], bh[nt][2]);
                    mma16816(acc[mt][nt*2+1], ah[mt], bh[nt][1], bh[nt][3]);
                    mma16816(acc[mt][nt*2+0], ah[mt], bl[nt][0], bl[nt][2]);
                    mma16816(acc[mt][nt*2+1], ah[mt], bl[nt][1], bl[nt][3]);
                    mma16816(acc[mt][nt*2+0], al[mt], bh[nt][0], bh[nt][2]);
                    mma16816(acc[mt][nt*2+1], al[mt], bh[nt][1], bh[nt][3]);
                }
        }
    }

    // ---- epilogue ----
    const int g = lane >> 2, t = lane & 3;
    #pragma unroll
    for (int mt = 0; mt < 2; mt++) {
        #pragma unroll
        for (int ntg = 0; ntg < 8; ntg++) {
            int gc = col0 + warp_n * 64 + ntg * 8 + t * 2;
            if (gc >= k) continue;
            #pragma unroll
            for (int half = 0; half < 2; half++) {
                int gr = row0 + warp_m * 32 + mt * 16 + g + half * 8;
                if (gr >= n) continue;
                float c0 = acc[mt][ntg][half * 2 + 0];
                float c1 = acc[mt][ntg][half * 2 + 1];
                if (EPI == 1) {
                    float2 x0 = *(const float2*)&A[(size_t)gr * m + gc];
                    c0 = fmaxf(beta * c0 + (1.0f - beta) * x0.x, 0.f);
                    c1 = fmaxf(beta * c1 + (1.0f - beta) * x0.y, 0.f);
                } else if (EPI == 2) {
                    float2 b = *(const float2*)&bias[gc];
                    c0 = fmaxf(c0 + b.x, 0.f);
                    c1 = fmaxf(c1 + b.y, 0.f);
                }
                *(float2*)&C[(size_t)gr * k + gc] = make_float2(c0, c1);
            }
        }
    }
}

// ---------------- pull-based GCN propagation ----------------
template <int D4, int MODE>
__global__ void prop_pull(const float4* __restrict__ h, float4* __restrict__ o,
                          const float* __restrict__ aux,
                          const int* __restrict__ off, const int* __restrict__ csr_s,
                          const float* __restrict__ csr_w) {
    constexpr int TPN = (D4 < 32) ? D4 : 32;
    constexpr int NPW = 32 / TPN;
    constexpr int R   = D4 / TPN;
    int gwarp = (blockIdx.x * blockDim.x + threadIdx.x) >> 5;
    int lane  = threadIdx.x & 31;
    int node  = gwarp * NPW + lane / TPN;
    int tl    = lane % TPN;
    if (node >= NN) return;

    float4 acc[R];
    #pragma unroll
    for (int r = 0; r < R; r++) acc[r] = make_float4(0.f, 0.f, 0.f, 0.f);

    int j0 = off[node], j1 = off[node + 1];
    int j = j0;
    for (; j + 1 < j1; j += 2) {
        int   s0 = csr_s[j],     s1 = csr_s[j + 1];
        float w0 = csr_w[j],     w1 = csr_w[j + 1];
        #pragma unroll
        for (int r = 0; r < R; r++) {
            float4 v0 = h[(size_t)s0 * D4 + tl + r * TPN];
            float4 v1 = h[(size_t)s1 * D4 + tl + r * TPN];
            acc[r].x += w0 * v0.x + w1 * v1.x;
            acc[r].y += w0 * v0.y + w1 * v1.y;
            acc[r].z += w0 * v0.z + w1 * v1.z;
            acc[r].w += w0 * v0.w + w1 * v1.w;
        }
    }
    if (j < j1) {
        int s0 = csr_s[j];
        float w0 = csr_w[j];
        #pragma unroll
        for (int r = 0; r < R; r++) {
            float4 v0 = h[(size_t)s0 * D4 + tl + r * TPN];
            acc[r].x += w0 * v0.x; acc[r].y += w0 * v0.y;
            acc[r].z += w0 * v0.z; acc[r].w += w0 * v0.w;
        }
    }

    const float4* aux4 = (const float4*)aux;
    #pragma unroll
    for (int r = 0; r < R; r++) {
        int c = tl + r * TPN;
        float4 v = acc[r];
        if (MODE == 0 || MODE == 2) {
            float4 b = aux4[c];
            v.x += b.x; v.y += b.y; v.z += b.z; v.w += b.w;
            if (MODE == 0) {
                v.x = fmaxf(v.x, 0.f); v.y = fmaxf(v.y, 0.f);
                v.z = fmaxf(v.z, 0.f); v.w = fmaxf(v.w, 0.f);
            }
        } else if (MODE == 1) {
            float4 x0 = aux4[(size_t)node * D4 + c];
            v.x = 0.5f * (v.x + x0.x); v.y = 0.5f * (v.y + x0.y);
            v.z = 0.5f * (v.z + x0.z); v.w = 0.5f * (v.w + x0.w);
        }
        o[(size_t)node * D4 + c] = v;
    }
}

// ---------------- GATv2 ----------------
__global__ void gat_logit(const float* __restrict__ xl, const float* __restrict__ xr,
                          const int* __restrict__ off, const int* __restrict__ cs,
                          const float* __restrict__ att, float* __restrict__ ea,
                          float4* __restrict__ amax4, float4* __restrict__ asum4) {
    int node = (blockIdx.x * blockDim.x + threadIdx.x) >> 5;
    int lane = threadIdx.x & 31;
    if (node >= NN) return;
    int j0 = off[node], j1 = off[node + 1];

    float xrh[4], atth[4];
    #pragma unroll
    for (int h = 0; h < 4; h++) {
        xrh[h]  = xr[(size_t)node * 128 + h * 32 + lane];
        atth[h] = att[h * 32 + lane];
    }
    float mx[4] = {-1e30f, -1e30f, -1e30f, -1e30f};
    float sm[4] = {0.f, 0.f, 0.f, 0.f};
    for (int j = j0; j < j1; j++) {
        int s = cs[j];
        const float* ls = xl + (size_t)s * 128;
        float a[4];
        #pragma unroll
        for (int h = 0; h < 4; h++) {
            float v = ls[h * 32 + lane] + xrh[h];
            v = (v > 0.0f) ? v : 0.2f * v;
            v *= atth[h];
            #pragma unroll
            for (int o = 16; o; o >>= 1) v += __shfl_xor_sync(0xffffffffu, v, o);
            a[h] = v;
            float nm = fmaxf(mx[h], v);
            sm[h] = sm[h] * __expf(mx[h] - nm) + __expf(v - nm);
            mx[h] = nm;
        }
        if (lane == 0)
            reinterpret_cast<float4*>(ea)[j] = make_float4(a[0], a[1], a[2], a[3]);
    }
    if (lane == 0) {
        amax4[node] = make_float4(mx[0], mx[1], mx[2], mx[3]);
        asum4[node] = make_float4(sm[0], sm[1], sm[2], sm[3]);
    }
}
__global__ void gat_gather(const float* __restrict__ ea, const float4* __restrict__ xl,
                           const int* __restrict__ off, const int* __restrict__ cs,
                           const float4* __restrict__ amax4, const float4* __restrict__ asum4,
                           const float* __restrict__ bg, float4* __restrict__ out) {
    int node = (blockIdx.x * blockDim.x + threadIdx.x) >> 5;
    int lane = threadIdx.x & 31;
    if (node >= NN) return;
    int j0 = off[node], j1 = off[node + 1];
    int h = lane >> 3;
    float4 mxv = amax4[node], smv = asum4[node];
    float mxh = (h == 0) ? mxv.x : (h == 1) ? mxv.y : (h == 2) ? mxv.z : mxv.w;
    float smh = (h == 0) ? smv.x : (h == 1) ? smv.y : (h == 2) ? smv.z : smv.w;
    float inv = 1.0f / (smh + 1e-16f);
    float4 acc = ((const float4*)bg)[lane];
    for (int j = j0; j < j1; j++) {
        int s = cs[j];
        float p = __expf(ea[(size_t)j * 4 + h] - mxh) * inv;
        float4 v = xl[(size_t)s * 32 + lane];
        acc.x += p * v.x; acc.y += p * v.y; acc.z += p * v.z; acc.w += p * v.w;
    }
    acc.x = fmaxf(acc.x, 0.f); acc.y = fmaxf(acc.y, 0.f);
    acc.z = fmaxf(acc.z, 0.f); acc.w = fmaxf(acc.w, 0.f);
    out[(size_t)node * 32 + lane] = acc;
}

// ---------------- host helpers ----------------
static inline int mpad32(int m) { return ((m + 31) / 32) * 32; }

static void gemm(const float* A, const __nv_bfloat16* Wt, float* C,
                 int n, int m, int k, int epi, float beta, const float* bias,
                 cudaStream_t st) {
    int mp = mpad32(m);
    dim3 grid(divup(k, 128), divup(n, 128));
    if (epi == 1)      gemm_mma<1><<<grid, 256, 0, st>>>(A, Wt, C, n, m, k, mp, beta, nullptr);
    else if (epi == 2) gemm_mma<2><<<grid, 256, 0, st>>>(A, Wt, C, n, m, k, mp, 0.0f, bias);
    else               gemm_mma<0><<<grid, 256, 0, st>>>(A, Wt, C, n, m, k, mp, 0.0f, nullptr);
}

template <int D4, int MODE>
static void prop_launch(const float* h, float* o, const float* aux,
                        const int* off, const int* cs, const float* cw) {
    constexpr int NPW = (D4 < 32) ? (32 / D4) : 1;
    int warps = divup(NN, NPW);
    prop_pull<D4, MODE><<<divup((long long)warps * 32, 256), 256>>>(
        (const float4*)h, (float4*)o, aux, off, cs, cw);
}

static cudaStream_t s_side = nullptr;
static cudaEvent_t  s_ev0, s_ev1, s_ev2, s_ev3;

// weight scratch offsets — mpad = mpad32(m) EVERYWHERE (bug fix: Wl/Wr were 64-padded)
#define WOFF_W1  0
#define WOFF_W2  (WOFF_W1  + 2 * 256 * 320)
#define WOFF_W3  (WOFF_W2  + 2 * 128 * 256)
#define WOFF_W4  (WOFF_W3  + 2 * 64 * 128)
#define WOFF_WL  (WOFF_W4  + 2 * 32 * 64)
#define WOFF_WR  (WOFF_WL  + 2 * 128 * 32)
#define WOFF_WC1 (WOFF_WR  + 2 * 128 * 32)
#define WOFF_W5  (WOFF_WC1 + 2 * 128 * 128)
#define WOFF_WC2 (WOFF_W5  + 2 * 256 * 128)
#define WOFF_WO  (WOFF_WC2 + 2 * 256 * 256)

extern "C" void kernel_launch(void* const* d_in, const int* in_sizes, int n_in,
                              void* d_out, int out_size) {
    if (!s_side) {
        cudaStreamCreateWithFlags(&s_side, cudaStreamNonBlocking);
        cudaEventCreateWithFlags(&s_ev0, cudaEventDisableTiming);
        cudaEventCreateWithFlags(&s_ev1, cudaEventDisableTiming);
        cudaEventCreateWithFlags(&s_ev2, cudaEventDisableTiming);
        cudaEventCreateWithFlags(&s_ev3, cudaEventDisableTiming);
    }
    const cudaStream_t MAIN = 0;

    const float* x   = (const float*)d_in[0];
    const int*   ei32= (const int*)d_in[1];
    const float* W1 = (const float*)d_in[2];  const float* b1 = (const float*)d_in[3];
    const float* W2 = (const float*)d_in[4];  const float* b2 = (const float*)d_in[5];
    const float* W3 = (const float*)d_in[6];  const float* b3 = (const float*)d_in[7];
    const float* W4 = (const float*)d_in[8];  const float* b4 = (const float*)d_in[9];
    const float* Wl = (const float*)d_in[10]; const float* Wr = (const float*)d_in[11];
    const float* att= (const float*)d_in[12]; const float* bg = (const float*)d_in[13];
    const float* Wc1= (const float*)d_in[14];
    const float* W5 = (const float*)d_in[15]; const float* b5 = (const float*)d_in[16];
    const float* Wc2= (const float*)d_in[17];
    const float* Wo = (const float*)d_in[18]; const float* bo = (const float*)d_in[19];
    float* out = (float*)d_out;

    float *x1, *x2, *A, *B, *C, *D, *ea, *amax, *asum, *dinv, *cw;
    int *src, *dst, *cnt, *off, *cur, *bsum, *cs;
    __nv_bfloat16* wt;
    cudaGetSymbolAddress((void**)&x1,   g_x1);
    cudaGetSymbolAddress((void**)&x2,   g_x2);
    cudaGetSymbolAddress((void**)&A,    g_A);
    cudaGetSymbolAddress((void**)&B,    g_B);
    cudaGetSymbolAddress((void**)&C,    g_C);
    cudaGetSymbolAddress((void**)&D,    g_D);
    cudaGetSymbolAddress((void**)&ea,   g_ea);
    cudaGetSymbolAddress((void**)&amax, g_amax);
    cudaGetSymbolAddress((void**)&asum, g_asum);
    cudaGetSymbolAddress((void**)&dinv, g_dinv);
    cudaGetSymbolAddress((void**)&src,  g_src);
    cudaGetSymbolAddress((void**)&dst,  g_dst);
    cudaGetSymbolAddress((void**)&cnt,  g_cnt);
    cudaGetSymbolAddress((void**)&off,  g_off);
    cudaGetSymbolAddress((void**)&cur,  g_cur);
    cudaGetSymbolAddress((void**)&bsum, g_bsum);
    cudaGetSymbolAddress((void**)&cs,   g_csr_s);
    cudaGetSymbolAddress((void**)&cw,   g_csr_w);
    cudaGetSymbolAddress((void**)&wt,   g_wt);

    const float BETA = logf(1.05f);

    // ---- head: detect(1), convert(2), splitW1(3), gemm1(4 <- profiled) ----
    k_detect<<<1, 256>>>(ei32);
    k_convert<<<divup(NE, 256), 256>>>(ei32, src, dst);
    k_splitw<<<divup(256 * 320, 256), 256>>>(W1, wt + WOFF_W1, 300, 256, 320);
    gemm(x, wt + WOFF_W1, A, NN, 300, 256, 0, 0.0f, nullptr, MAIN);
    cudaEventRecord(s_ev0, MAIN);
    cudaStreamWaitEvent(s_side, s_ev0, 0);

    // side stream: remaining weight splits + CSR build (mpad = mpad32(m) everywhere)
    k_splitw<<<divup(128 * 256, 256), 256, 0, s_side>>>(W2,  wt + WOFF_W2,  256, 128, 256);
    k_splitw<<<divup(64 * 128, 256),  256, 0, s_side>>>(W3,  wt + WOFF_W3,  128, 64, 128);
    k_splitw<<<divup(32 * 64, 256),   256, 0, s_side>>>(W4,  wt + WOFF_W4,  64, 32, 64);
    k_splitw<<<divup(128 * 32, 256),  256, 0, s_side>>>(Wl,  wt + WOFF_WL,  32, 128, 32);
    k_splitw<<<divup(128 * 32, 256),  256, 0, s_side>>>(Wr,  wt + WOFF_WR,  32, 128, 32);
    k_splitw<<<divup(128 * 128, 256), 256, 0, s_side>>>(Wc1, wt + WOFF_WC1, 128, 128, 128);
    k_splitw<<<divup(256 * 128, 256), 256, 0, s_side>>>(W5,  wt + WOFF_W5,  128, 256, 128);
    k_splitw<<<divup(256 * 256, 256), 256, 0, s_side>>>(Wc2, wt + WOFF_WC2, 256, 256, 256);
    k_splitw<<<divup(128 * 256, 256), 256, 0, s_side>>>(Wo,  wt + WOFF_WO,  256, 128, 256);
    k_fill_i<<<divup(NN, 256), 256, 0, s_side>>>(cnt, NN, 1);
    k_count<<<divup(NE, 256), 256, 0, s_side>>>(dst, cnt);
    k_dinv<<<divup(NN, 256), 256, 0, s_side>>>(cnt, dinv);
    scan1<<<SCAN_NB, SCAN_BS, 0, s_side>>>(cnt, bsum);
    scan2<<<1, 1024, 0, s_side>>>(bsum);
    scan3<<<SCAN_NB, SCAN_BS, 0, s_side>>>(cnt, bsum, off);
    k_copy_i<<<divup(NN, 256), 256, 0, s_side>>>(off, cur, NN);
    k_bucket<<<divup(NE2, 256), 256, 0, s_side>>>(src, dst, dinv, cur, cs, cw);
    cudaEventRecord(s_ev1, s_side);
    cudaStreamWaitEvent(MAIN, s_ev1, 0);

    // ---- x1 = relu(prop(x@W1)+b1) ----
    prop_launch<64, 0>(A, x1, b1, off, cs, cw);

    // ---- x2 = relu(prop(x1@W2)+b2) ----
    gemm(x1, wt + WOFF_W2, A, NN, 256, 128, 0, 0.0f, nullptr, MAIN);
    prop_launch<32, 0>(A, x2, b2, off, cs, cw);

    // ---- x3 = relu(prop(x2@W3)+b3)  (64) ----
    gemm(x2, wt + WOFF_W3, A, NN, 128, 64, 0, 0.0f, nullptr, MAIN);
    prop_launch<16, 0>(A, B, b3, off, cs, cw);

    // ---- x3 = relu(prop(x3@W4)+b4)  (32) ----
    gemm(B, wt + WOFF_W4, A, NN, 64, 32, 0, 0.0f, nullptr, MAIN);
    prop_launch<8, 0>(A, B, b4, off, cs, cw);

    // ---- GATv2 (128); xl=C (main), xr=A (side) ----
    cudaEventRecord(s_ev2, MAIN);
    cudaStreamWaitEvent(s_side, s_ev2, 0);
    gemm(B, wt + WOFF_WR, A, NN, 32, 128, 0, 0.0f, nullptr, s_side);
    cudaEventRecord(s_ev3, s_side);
    gemm(B, wt + WOFF_WL, C, NN, 32, 128, 0, 0.0f, nullptr, MAIN);
    cudaStreamWaitEvent(MAIN, s_ev3, 0);
    gat_logit<<<divup((long long)NN * 32, 256), 256>>>(C, A, off, cs, att, ea,
                                                       (float4*)amax, (float4*)asum);
    gat_gather<<<divup((long long)NN * 32, 256), 256>>>(ea, (const float4*)C, off, cs,
                                                        (const float4*)amax,
                                                        (const float4*)asum, bg, (float4*)D);

    // ---- GCN2 #1 with x0=x2 (128) ----
    prop_launch<32, 1>(D, A, x2, off, cs, cw);
    gemm(A, wt + WOFF_WC1, B, NN, 128, 128, 1, BETA, nullptr, MAIN);

    // ---- x3 = relu(prop(B)@W5 + b5)  (prop commuted to 128-d) ----
    prop_launch<32, 3>(B, A, nullptr, off, cs, cw);
    gemm(A, wt + WOFF_W5, C, NN, 128, 256, 2, 0.0f, b5, MAIN);

    // ---- GCN2 #2 with x0=x1 (256) ----
    prop_launch<64, 1>(C, A, x1, off, cs, cw);
    gemm(A, wt + WOFF_WC2, B, NN, 256, 256, 1, BETA, nullptr, MAIN);

    // ---- out = prop(x3@Wo) + bo ----
    gemm(B, wt + WOFF_WO, A, NN, 256, 128, 0, 0.0f, nullptr, MAIN);
    prop_launch<32, 2>(A, out, bo, off, cs, cw);
}

// round 11
// speedup vs baseline: 3.3501x; 1.1482x over previous
#include <cuda_runtime.h>
#include <cuda_bf16.h>
#include <cstdint>
#include <math.h>

#define NN 50000
#define NE 800000
#define NE2 850000
#define SCAN_BS 512
#define SCAN_NB ((NN + SCAN_BS - 1) / SCAN_BS)

// ---------------- device scratch ----------------
__device__ __align__(16) float g_x1[(size_t)NN * 256];
__device__ __align__(16) float g_x2[(size_t)NN * 128];
__device__ __align__(16) float g_A [(size_t)NN * 256];
__device__ __align__(16) float g_B [(size_t)NN * 256];
__device__ __align__(16) float g_C [(size_t)NN * 256];
__device__ __align__(16) float g_D [(size_t)NN * 128];
__device__ float    g_dinv[NN];
__device__ int      g_src[NE];
__device__ int      g_dst[NE];
__device__ int      g_cnt[NN];
__device__ int      g_off[NN + 1];
__device__ int      g_cur[NN];
__device__ int      g_bsum[SCAN_NB + 32];
__device__ int      g_csr_s[NE2];
__device__ float    g_csr_w[NE2];
__device__ int      g_eflag[1];
// split-bf16 transposed weights: [k][mpad] K-major, hi plane then lo plane
__device__ __align__(16) __nv_bfloat16 g_wt[600000];

static inline int divup(long long a, int b) { return (int)((a + b - 1) / b); }

// ---------------- PTX helpers (plain-sm_100 legal) ----------------
__device__ __forceinline__ uint32_t smem_u32(const void* p) {
    uint32_t a;
    asm("{ .reg .u64 t; cvta.to.shared.u64 t, %1; cvt.u32.u64 %0, t; }" : "=r"(a) : "l"(p));
    return a;
}
__device__ __forceinline__ void ldm_x4(uint32_t (&r)[4], uint32_t addr) {
    asm volatile("ldmatrix.sync.aligned.m8n8.x4.shared.b16 {%0,%1,%2,%3}, [%4];"
                 : "=r"(r[0]), "=r"(r[1]), "=r"(r[2]), "=r"(r[3]) : "r"(addr));
}
__device__ __forceinline__ void mma16816(float (&d)[4], const uint32_t (&a)[4],
                                         uint32_t b0, uint32_t b1) {
    asm volatile(
        "mma.sync.aligned.m16n8k16.row.col.f32.bf16.bf16.f32 "
        "{%0,%1,%2,%3}, {%4,%5,%6,%7}, {%8,%9}, {%0,%1,%2,%3};"
        : "+f"(d[0]), "+f"(d[1]), "+f"(d[2]), "+f"(d[3])
        : "r"(a[0]), "r"(a[1]), "r"(a[2]), "r"(a[3]), "r"(b0), "r"(b1));
}

// ---------------- edge-index dtype detection + conversion ----------------
__global__ void k_detect(const int* __restrict__ ei32) {
    __shared__ int cnt;
    if (threadIdx.x == 0) cnt = 0;
    __syncthreads();
    int nz = 0;
    for (int i = threadIdx.x; i < 2048; i += blockDim.x)
        if (ei32[2 * i + 1] != 0) nz++;
    atomicAdd(&cnt, nz);
    __syncthreads();
    if (threadIdx.x == 0) g_eflag[0] = (cnt == 0) ? 1 : 0;
}
__global__ void k_convert(const int* __restrict__ ei32,
                          int* __restrict__ src, int* __restrict__ dst) {
    int e = blockIdx.x * blockDim.x + threadIdx.x;
    if (e >= NE) return;
    int is64 = g_eflag[0];
    int s, d;
    if (is64) { s = ei32[2 * e]; d = ei32[2 * (NE + e)]; }
    else      { s = ei32[e];     d = ei32[NE + e]; }
    s = min(max(s, 0), NN - 1);
    d = min(max(d, 0), NN - 1);
    src[e] = s; dst[e] = d;
}

// ---------------- weight pre-transpose + bf16 split ----------------
__global__ void k_splitw(const float* __restrict__ W, __nv_bfloat16* __restrict__ wt,
                         int m, int k, int mpad) {
    int idx = blockIdx.x * blockDim.x + threadIdx.x;
    int tot = k * mpad;
    if (idx >= tot) return;
    int j = idx / mpad, kk = idx % mpad;
    float f = (kk < m) ? W[(size_t)kk * k + j] : 0.0f;
    __nv_bfloat16 h = __float2bfloat16(f);
    __nv_bfloat16 l = __float2bfloat16(f - __bfloat162float(h));
    wt[idx] = h;
    wt[tot + idx] = l;
}

// ---------------- CSR build ----------------
__global__ void k_fill_i(int* p, int n, int v) {
    int i = blockIdx.x * blockDim.x + threadIdx.x;
    if (i < n) p[i] = v;
}
__global__ void k_count(const int* __restrict__ dst, int* __restrict__ cnt) {
    int e = blockIdx.x * blockDim.x + threadIdx.x;
    if (e < NE) atomicAdd(&cnt[dst[e]], 1);
}
__global__ void k_dinv(const int* __restrict__ cnt, float* __restrict__ dinv) {
    int i = blockIdx.x * blockDim.x + threadIdx.x;
    if (i < NN) dinv[i] = rsqrtf((float)cnt[i]);
}
__global__ void scan1(const int* __restrict__ cnt, int* __restrict__ bsum) {
    __shared__ int sh[SCAN_BS];
    int i = blockIdx.x * SCAN_BS + threadIdx.x;
    sh[threadIdx.x] = (i < NN) ? cnt[i] : 0;
    __syncthreads();
    for (int s = SCAN_BS / 2; s; s >>= 1) {
        if (threadIdx.x < s) sh[threadIdx.x] += sh[threadIdx.x + s];
        __syncthreads();
    }
    if (threadIdx.x == 0) bsum[blockIdx.x] = sh[0];
}
__global__ void scan2(int* __restrict__ bsum) {
    __shared__ int sh[1024];
    int v = (threadIdx.x < SCAN_NB) ? bsum[threadIdx.x] : 0;
    sh[threadIdx.x] = v;
    __syncthreads();
    for (int o = 1; o < 1024; o <<= 1) {
        int t = (threadIdx.x >= o) ? sh[threadIdx.x - o] : 0;
        __syncthreads();
        sh[threadIdx.x] += t;
        __syncthreads();
    }
    if (threadIdx.x < SCAN_NB) bsum[threadIdx.x] = sh[threadIdx.x] - v;
}
__global__ void scan3(const int* __restrict__ cnt, const int* __restrict__ bsum,
                      int* __restrict__ off) {
    __shared__ int sh[SCAN_BS];
    int i = blockIdx.x * SCAN_BS + threadIdx.x;
    int v = (i < NN) ? cnt[i] : 0;
    sh[threadIdx.x] = v;
    __syncthreads();
    for (int o = 1; o < SCAN_BS; o <<= 1) {
        int t = (threadIdx.x >= o) ? sh[threadIdx.x - o] : 0;
        __syncthreads();
        sh[threadIdx.x] += t;
        __syncthreads();
    }
    if (i <= NN) off[i] = bsum[blockIdx.x] + sh[threadIdx.x] - v;
}
__global__ void k_copy_i(const int* __restrict__ a, int* __restrict__ b, int n) {
    int i = blockIdx.x * blockDim.x + threadIdx.x;
    if (i < n) b[i] = a[i];
}
__global__ void k_bucket(const int* __restrict__ src, const int* __restrict__ dst,
                         const float* __restrict__ dinv, int* __restrict__ cur,
                         int* __restrict__ cs, float* __restrict__ cw) {
    int t = blockIdx.x * blockDim.x + threadIdx.x;
    if (t >= NE2) return;
    int s, d;
    if (t < NE) { s = src[t]; d = dst[t]; }
    else        { s = d = t - NE; }
    int pos = atomicAdd(&cur[d], 1);
    cs[pos] = s;
    cw[pos] = dinv[s] * dinv[d];
}

// ---------------- mma.sync bf16x3 GEMM: C[n,k] = A[n,m] @ W[m,k] ----------------
// Block 128x128, 8 warps (4 M x 2 N), warp tile 32x64, K-tile 32 (2 x k16).
// EPI: 0 none, 1 GCN2 relu((1-b)A + b*AW) (m==k), 2 relu(AW + bias)
#define LDS_B 80
template <int EPI>
__global__ __launch_bounds__(256) void gemm_mma(
    const float* __restrict__ A, const __nv_bfloat16* __restrict__ Wt,
    float* __restrict__ C, int n, int m, int k, int mpad, float beta,
    const float* __restrict__ bias) {
    __shared__ __align__(16) char sAh[128 * LDS_B];
    __shared__ __align__(16) char sAl[128 * LDS_B];
    __shared__ __align__(16) char sBh[128 * LDS_B];
    __shared__ __align__(16) char sBl[128 * LDS_B];

    const int tid  = threadIdx.x;
    const int wid  = tid >> 5, lane = tid & 31;
    const int warp_m = wid & 3, warp_n = wid >> 2;
    const int row0 = blockIdx.y * 128;
    const int col0 = blockIdx.x * 128;
    const int planeoff = k * mpad;

    const uint32_t ah_b = smem_u32(sAh), al_b = smem_u32(sAl);
    const uint32_t bh_b = smem_u32(sBh), bl_b = smem_u32(sBl);
    const int lr = lane & 15, lc = lane >> 4;
    const uint32_t a_off = (uint32_t)(warp_m * 32 + lr) * LDS_B + lc * 16;
    const uint32_t b_off = (uint32_t)(warp_n * 64 + lr) * LDS_B + lc * 16;

    float acc[2][8][4];
    #pragma unroll
    for (int i = 0; i < 2; i++)
        #pragma unroll
        for (int j = 0; j < 8; j++)
            #pragma unroll
            for (int r = 0; r < 4; r++) acc[i][j][r] = 0.0f;

    const uint4 Z4 = make_uint4(0, 0, 0, 0);

    for (int kt = 0; kt < mpad; kt += 32) {
        __syncthreads();
        // ---- A tile: 128 x 32 fp32 -> bf16 hi/lo ----
        #pragma unroll
        for (int i = 0; i < 4; i++) {
            int idx = tid + i * 256;
            int r = idx >> 3, q = idx & 7;
            int gr = row0 + r, gk = kt + q * 4;
            float4 v = make_float4(0.f, 0.f, 0.f, 0.f);
            if (gr < n && gk < m) v = *(const float4*)&A[(size_t)gr * m + gk];
            __nv_bfloat16 h0 = __float2bfloat16(v.x), h1 = __float2bfloat16(v.y);
            __nv_bfloat16 h2 = __float2bfloat16(v.z), h3 = __float2bfloat16(v.w);
            __nv_bfloat16 l0 = __float2bfloat16(v.x - __bfloat162float(h0));
            __nv_bfloat16 l1 = __float2bfloat16(v.y - __bfloat162float(h1));
            __nv_bfloat16 l2 = __float2bfloat16(v.z - __bfloat162float(h2));
            __nv_bfloat16 l3 = __float2bfloat16(v.w - __bfloat162float(h3));
            __nv_bfloat162 hp0 = {h0, h1}, hp1 = {h2, h3};
            __nv_bfloat162 lp0 = {l0, l1}, lp1 = {l2, l3};
            uint2 uh = make_uint2(*(uint32_t*)&hp0, *(uint32_t*)&hp1);
            uint2 ul = make_uint2(*(uint32_t*)&lp0, *(uint32_t*)&lp1);
            *(uint2*)(sAh + r * LDS_B + q * 8) = uh;
            *(uint2*)(sAl + r * LDS_B + q * 8) = ul;
        }
        // ---- B tile: 128 n-rows x 32 k bf16 (pre-split) ----
        #pragma unroll
        for (int i = 0; i < 2; i++) {
            int idx = tid + i * 256;
            int j = idx >> 2, kq = idx & 3;
            int gj = col0 + j;
            uint4 vh = Z4, vl = Z4;
            if (gj < k) {
                size_t g = (size_t)gj * mpad + kt + kq * 8;
                vh = *(const uint4*)&Wt[g];
                vl = *(const uint4*)&Wt[planeoff + g];
            }
            *(uint4*)(sBh + j * LDS_B + kq * 16) = vh;
            *(uint4*)(sBl + j * LDS_B + kq * 16) = vl;
        }
        __syncthreads();

        #pragma unroll
        for (int ks = 0; ks < 2; ks++) {
            const uint32_t kb2 = ks * 32;
            uint32_t ah[2][4], al[2][4], bh[4][4], bl[4][4];
            #pragma unroll
            for (int mt = 0; mt < 2; mt++) {
                ldm_x4(ah[mt], ah_b + a_off + mt * (16 * LDS_B) + kb2);
                ldm_x4(al[mt], al_b + a_off + mt * (16 * LDS_B) + kb2);
            }
            #pragma unroll
            for (int nt = 0; nt < 4; nt++) {
                ldm_x4(bh[nt], bh_b + b_off + nt * (16 * LDS_B) + kb2);
                ldm_x4(bl[nt], bl_b + b_off + nt * (16 * LDS_B) + kb2);
            }
            #pragma unroll
            for (int mt = 0; mt < 2; mt++)
                #pragma unroll
                for (int nt = 0; nt < 4; nt++) {
                    mma16816(acc[mt][nt*2+0], ah[mt], bh[nt][0], bh[nt][2]);
                    mma16816(acc[mt][nt*2+1], ah[mt], bh[nt][1], bh[nt][3]);
                    mma16816(acc[mt][nt*2+0], ah[mt], bl[nt][0], bl[nt][2]);
                    mma16816(acc[mt][nt*2+1], ah[mt], bl[nt][1], bl[nt][3]);
                    mma16816(acc[mt][nt*2+0], al[mt], bh[nt][0], bh[nt][2]);
                    mma16816(acc[mt][nt*2+1], al[mt], bh[nt][1], bh[nt][3]);
                }
        }
    }

    // ---- epilogue ----
    const int g = lane >> 2, t = lane & 3;
    #pragma unroll
    for (int mt = 0; mt < 2; mt++) {
        #pragma unroll
        for (int ntg = 0; ntg < 8; ntg++) {
            int gc = col0 + warp_n * 64 + ntg * 8 + t * 2;
            if (gc >= k) continue;
            #pragma unroll
            for (int half = 0; half < 2; half++) {
                int gr = row0 + warp_m * 32 + mt * 16 + g + half * 8;
                if (gr >= n) continue;
                float c0 = acc[mt][ntg][half * 2 + 0];
                float c1 = acc[mt][ntg][half * 2 + 1];
                if (EPI == 1) {
                    float2 x0 = *(const float2*)&A[(size_t)gr * m + gc];
                    c0 = fmaxf(beta * c0 + (1.0f - beta) * x0.x, 0.f);
                    c1 = fmaxf(beta * c1 + (1.0f - beta) * x0.y, 0.f);
                } else if (EPI == 2) {
                    float2 b = *(const float2*)&bias[gc];
                    c0 = fmaxf(c0 + b.x, 0.f);
                    c1 = fmaxf(c1 + b.y, 0.f);
                }
                *(float2*)&C[(size_t)gr * k + gc] = make_float2(c0, c1);
            }
        }
    }
}

// ---------------- pull-based GCN propagation (unroll 4 for MLP) ----------------
// MODE 0: relu(acc+bias)  MODE 1: 0.5*(acc+x0)  MODE 2: acc+bias  MODE 3: acc
template <int D4, int MODE>
__global__ void prop_pull(const float4* __restrict__ h, float4* __restrict__ o,
                          const float* __restrict__ aux,
                          const int* __restrict__ off, const int* __restrict__ csr_s,
                          const float* __restrict__ csr_w) {
    constexpr int TPN = (D4 < 32) ? D4 : 32;
    constexpr int NPW = 32 / TPN;
    constexpr int R   = D4 / TPN;
    int gwarp = (blockIdx.x * blockDim.x + threadIdx.x) >> 5;
    int lane  = threadIdx.x & 31;
    int node  = gwarp * NPW + lane / TPN;
    int tl    = lane % TPN;
    if (node >= NN) return;

    float4 acc[R];
    #pragma unroll
    for (int r = 0; r < R; r++) acc[r] = make_float4(0.f, 0.f, 0.f, 0.f);

    int j0 = off[node], j1 = off[node + 1];
    int j = j0;
    for (; j + 3 < j1; j += 4) {
        int   s0 = csr_s[j],   s1 = csr_s[j+1], s2 = csr_s[j+2], s3 = csr_s[j+3];
        float w0 = csr_w[j],   w1 = csr_w[j+1], w2 = csr_w[j+2], w3 = csr_w[j+3];
        #pragma unroll
        for (int r = 0; r < R; r++) {
            float4 v0 = h[(size_t)s0 * D4 + tl + r * TPN];
            float4 v1 = h[(size_t)s1 * D4 + tl + r * TPN];
            float4 v2 = h[(size_t)s2 * D4 + tl + r * TPN];
            float4 v3 = h[(size_t)s3 * D4 + tl + r * TPN];
            acc[r].x += w0*v0.x + w1*v1.x + w2*v2.x + w3*v3.x;
            acc[r].y += w0*v0.y + w1*v1.y + w2*v2.y + w3*v3.y;
            acc[r].z += w0*v0.z + w1*v1.z + w2*v2.z + w3*v3.z;
            acc[r].w += w0*v0.w + w1*v1.w + w2*v2.w + w3*v3.w;
        }
    }
    for (; j < j1; j++) {
        int s0 = csr_s[j];
        float w0 = csr_w[j];
        #pragma unroll
        for (int r = 0; r < R; r++) {
            float4 v0 = h[(size_t)s0 * D4 + tl + r * TPN];
            acc[r].x += w0 * v0.x; acc[r].y += w0 * v0.y;
            acc[r].z += w0 * v0.z; acc[r].w += w0 * v0.w;
        }
    }

    const float4* aux4 = (const float4*)aux;
    #pragma unroll
    for (int r = 0; r < R; r++) {
        int c = tl + r * TPN;
        float4 v = acc[r];
        if (MODE == 0 || MODE == 2) {
            float4 b = aux4[c];
            v.x += b.x; v.y += b.y; v.z += b.z; v.w += b.w;
            if (MODE == 0) {
                v.x = fmaxf(v.x, 0.f); v.y = fmaxf(v.y, 0.f);
                v.z = fmaxf(v.z, 0.f); v.w = fmaxf(v.w, 0.f);
            }
        } else if (MODE == 1) {
            float4 x0 = aux4[(size_t)node * D4 + c];
            v.x = 0.5f * (v.x + x0.x); v.y = 0.5f * (v.y + x0.y);
            v.z = 0.5f * (v.z + x0.z); v.w = 0.5f * (v.w + x0.w);
        }
        o[(size_t)node * D4 + c] = v;
    }
}

// ---------------- GATv2: fully fused flash-softmax, one edge pass ----------------
// one warp per dst node. Lane l holds float4 cols 4l..4l+3 (head = l>>3).
// Per edge: one float4 gather; per-head logit via 8-lane reduction; online
// softmax rescale of the accumulator. out = acc/sum + bias, relu.
__global__ void gat_fused(const float4* __restrict__ xl4, const float4* __restrict__ xr4,
                          const int* __restrict__ off, const int* __restrict__ cs,
                          const float4* __restrict__ att4, const float* __restrict__ bg,
                          float4* __restrict__ out) {
    int node = (blockIdx.x * blockDim.x + threadIdx.x) >> 5;
    int lane = threadIdx.x & 31;
    if (node >= NN) return;
    int j0 = off[node], j1 = off[node + 1];

    float4 xr = xr4[(size_t)node * 32 + lane];
    float4 at = att4[lane];

    float m = -1e30f, s = 0.0f;
    float4 acc = make_float4(0.f, 0.f, 0.f, 0.f);

    for (int j = j0; j < j1; j++) {
        int sn = cs[j];
        float4 v = xl4[(size_t)sn * 32 + lane];
        // leaky-relu(v + xr) dot att (this lane's 4 cols, all in own head)
        float e0 = v.x + xr.x; e0 = (e0 > 0.f) ? e0 : 0.2f * e0;
        float e1 = v.y + xr.y; e1 = (e1 > 0.f) ? e1 : 0.2f * e1;
        float e2 = v.z + xr.z; e2 = (e2 > 0.f) ? e2 : 0.2f * e2;
        float e3 = v.w + xr.w; e3 = (e3 > 0.f) ? e3 : 0.2f * e3;
        float p = e0 * at.x + e1 * at.y + e2 * at.z + e3 * at.w;
        // reduce within the 8-lane head group
        p += __shfl_xor_sync(0xffffffffu, p, 1);
        p += __shfl_xor_sync(0xffffffffu, p, 2);
        p += __shfl_xor_sync(0xffffffffu, p, 4);
        // online softmax update
        float nm = fmaxf(m, p);
        float r  = __expf(m - nm);     // 0 on first iter (m = -1e30)
        float w  = __expf(p - nm);
        s = s * r + w;
        acc.x = acc.x * r + w * v.x;
        acc.y = acc.y * r + w * v.y;
        acc.z = acc.z * r + w * v.z;
        acc.w = acc.w * r + w * v.w;
        m = nm;
    }
    float inv = 1.0f / (s + 1e-16f);
    float4 b = ((const float4*)bg)[lane];
    acc.x = fmaxf(acc.x * inv + b.x, 0.f);
    acc.y = fmaxf(acc.y * inv + b.y, 0.f);
    acc.z = fmaxf(acc.z * inv + b.z, 0.f);
    acc.w = fmaxf(acc.w * inv + b.w, 0.f);
    out[(size_t)node * 32 + lane] = acc;
}

// ---------------- host helpers ----------------
static inline int mpad32(int m) { return ((m + 31) / 32) * 32; }

static void gemm(const float* A, const __nv_bfloat16* Wt, float* C,
                 int n, int m, int k, int epi, float beta, const float* bias,
                 cudaStream_t st) {
    int mp = mpad32(m);
    dim3 grid(divup(k, 128), divup(n, 128));
    if (epi == 1)      gemm_mma<1><<<grid, 256, 0, st>>>(A, Wt, C, n, m, k, mp, beta, nullptr);
    else if (epi == 2) gemm_mma<2><<<grid, 256, 0, st>>>(A, Wt, C, n, m, k, mp, 0.0f, bias);
    else               gemm_mma<0><<<grid, 256, 0, st>>>(A, Wt, C, n, m, k, mp, 0.0f, nullptr);
}

template <int D4, int MODE>
static void prop_launch(const float* h, float* o, const float* aux,
                        const int* off, const int* cs, const float* cw) {
    constexpr int NPW = (D4 < 32) ? (32 / D4) : 1;
    int warps = divup(NN, NPW);
    prop_pull<D4, MODE><<<divup((long long)warps * 32, 256), 256>>>(
        (const float4*)h, (float4*)o, aux, off, cs, cw);
}

static cudaStream_t s_side = nullptr;
static cudaEvent_t  s_ev0, s_ev1, s_ev2, s_ev3;

#define WOFF_W1  0
#define WOFF_W2  (WOFF_W1  + 2 * 256 * 320)
#define WOFF_W3  (WOFF_W2  + 2 * 128 * 256)
#define WOFF_W4  (WOFF_W3  + 2 * 64 * 128)
#define WOFF_WL  (WOFF_W4  + 2 * 32 * 64)
#define WOFF_WR  (WOFF_WL  + 2 * 128 * 32)
#define WOFF_WC1 (WOFF_WR  + 2 * 128 * 32)
#define WOFF_W5  (WOFF_WC1 + 2 * 128 * 128)
#define WOFF_WC2 (WOFF_W5  + 2 * 256 * 128)
#define WOFF_WO  (WOFF_WC2 + 2 * 256 * 256)

extern "C" void kernel_launch(void* const* d_in, const int* in_sizes, int n_in,
                              void* d_out, int out_size) {
    if (!s_side) {
        cudaStreamCreateWithFlags(&s_side, cudaStreamNonBlocking);
        cudaEventCreateWithFlags(&s_ev0, cudaEventDisableTiming);
        cudaEventCreateWithFlags(&s_ev1, cudaEventDisableTiming);
        cudaEventCreateWithFlags(&s_ev2, cudaEventDisableTiming);
        cudaEventCreateWithFlags(&s_ev3, cudaEventDisableTiming);
    }
    const cudaStream_t MAIN = 0;

    const float* x   = (const float*)d_in[0];
    const int*   ei32= (const int*)d_in[1];
    const float* W1 = (const float*)d_in[2];  const float* b1 = (const float*)d_in[3];
    const float* W2 = (const float*)d_in[4];  const float* b2 = (const float*)d_in[5];
    const float* W3 = (const float*)d_in[6];  const float* b3 = (const float*)d_in[7];
    const float* W4 = (const float*)d_in[8];  const float* b4 = (const float*)d_in[9];
    const float* Wl = (const float*)d_in[10]; const float* Wr = (const float*)d_in[11];
    const float* att= (const float*)d_in[12]; const float* bg = (const float*)d_in[13];
    const float* Wc1= (const float*)d_in[14];
    const float* W5 = (const float*)d_in[15]; const float* b5 = (const float*)d_in[16];
    const float* Wc2= (const float*)d_in[17];
    const float* Wo = (const float*)d_in[18]; const float* bo = (const float*)d_in[19];
    float* out = (float*)d_out;

    float *x1, *x2, *A, *B, *C, *D, *dinv, *cw;
    int *src, *dst, *cnt, *off, *cur, *bsum, *cs;
    __nv_bfloat16* wt;
    cudaGetSymbolAddress((void**)&x1,   g_x1);
    cudaGetSymbolAddress((void**)&x2,   g_x2);
    cudaGetSymbolAddress((void**)&A,    g_A);
    cudaGetSymbolAddress((void**)&B,    g_B);
    cudaGetSymbolAddress((void**)&C,    g_C);
    cudaGetSymbolAddress((void**)&D,    g_D);
    cudaGetSymbolAddress((void**)&dinv, g_dinv);
    cudaGetSymbolAddress((void**)&src,  g_src);
    cudaGetSymbolAddress((void**)&dst,  g_dst);
    cudaGetSymbolAddress((void**)&cnt,  g_cnt);
    cudaGetSymbolAddress((void**)&off,  g_off);
    cudaGetSymbolAddress((void**)&cur,  g_cur);
    cudaGetSymbolAddress((void**)&bsum, g_bsum);
    cudaGetSymbolAddress((void**)&cs,   g_csr_s);
    cudaGetSymbolAddress((void**)&cw,   g_csr_w);
    cudaGetSymbolAddress((void**)&wt,   g_wt);

    const float BETA = logf(1.05f);

    // ---- head: detect(1), convert(2), splitW1(3), gemm1(4 <- profiled) ----
    k_detect<<<1, 256>>>(ei32);
    k_convert<<<divup(NE, 256), 256>>>(ei32, src, dst);
    k_splitw<<<divup(256 * 320, 256), 256>>>(W1, wt + WOFF_W1, 300, 256, 320);
    gemm(x, wt + WOFF_W1, A, NN, 300, 256, 0, 0.0f, nullptr, MAIN);
    cudaEventRecord(s_ev0, MAIN);
    cudaStreamWaitEvent(s_side, s_ev0, 0);

    // side stream: remaining weight splits + CSR build
    k_splitw<<<divup(128 * 256, 256), 256, 0, s_side>>>(W2,  wt + WOFF_W2,  256, 128, 256);
    k_splitw<<<divup(64 * 128, 256),  256, 0, s_side>>>(W3,  wt + WOFF_W3,  128, 64, 128);
    k_splitw<<<divup(32 * 64, 256),   256, 0, s_side>>>(W4,  wt + WOFF_W4,  64, 32, 64);
    k_splitw<<<divup(128 * 32, 256),  256, 0, s_side>>>(Wl,  wt + WOFF_WL,  32, 128, 32);
    k_splitw<<<divup(128 * 32, 256),  256, 0, s_side>>>(Wr,  wt + WOFF_WR,  32, 128, 32);
    k_splitw<<<divup(128 * 128, 256), 256, 0, s_side>>>(Wc1, wt + WOFF_WC1, 128, 128, 128);
    k_splitw<<<divup(256 * 128, 256), 256, 0, s_side>>>(W5,  wt + WOFF_W5,  128, 256, 128);
    k_splitw<<<divup(256 * 256, 256), 256, 0, s_side>>>(Wc2, wt + WOFF_WC2, 256, 256, 256);
    k_splitw<<<divup(128 * 256, 256), 256, 0, s_side>>>(Wo,  wt + WOFF_WO,  256, 128, 256);
    k_fill_i<<<divup(NN, 256), 256, 0, s_side>>>(cnt, NN, 1);
    k_count<<<divup(NE, 256), 256, 0, s_side>>>(dst, cnt);
    k_dinv<<<divup(NN, 256), 256, 0, s_side>>>(cnt, dinv);
    scan1<<<SCAN_NB, SCAN_BS, 0, s_side>>>(cnt, bsum);
    scan2<<<1, 1024, 0, s_side>>>(bsum);
    scan3<<<SCAN_NB, SCAN_BS, 0, s_side>>>(cnt, bsum, off);
    k_copy_i<<<divup(NN, 256), 256, 0, s_side>>>(off, cur, NN);
    k_bucket<<<divup(NE2, 256), 256, 0, s_side>>>(src, dst, dinv, cur, cs, cw);
    cudaEventRecord(s_ev1, s_side);
    cudaStreamWaitEvent(MAIN, s_ev1, 0);

    // ---- x1 = relu(prop(x@W1)+b1) ----
    prop_launch<64, 0>(A, x1, b1, off, cs, cw);

    // ---- x2 = relu(prop(x1@W2)+b2) ----
    gemm(x1, wt + WOFF_W2, A, NN, 256, 128, 0, 0.0f, nullptr, MAIN);
    prop_launch<32, 0>(A, x2, b2, off, cs, cw);

    // ---- x3 = relu(prop(x2@W3)+b3)  (64) ----
    gemm(x2, wt + WOFF_W3, A, NN, 128, 64, 0, 0.0f, nullptr, MAIN);
    prop_launch<16, 0>(A, B, b3, off, cs, cw);

    // ---- x3 = relu(prop(x3@W4)+b4)  (32) ----
    gemm(B, wt + WOFF_W4, A, NN, 64, 32, 0, 0.0f, nullptr, MAIN);
    prop_launch<8, 0>(A, B, b4, off, cs, cw);

    // ---- GATv2 (128); xl=C (main), xr=A (side) — fused flash-softmax ----
    cudaEventRecord(s_ev2, MAIN);
    cudaStreamWaitEvent(s_side, s_ev2, 0);
    gemm(B, wt + WOFF_WR, A, NN, 32, 128, 0, 0.0f, nullptr, s_side);
    cudaEventRecord(s_ev3, s_side);
    gemm(B, wt + WOFF_WL, C, NN, 32, 128, 0, 0.0f, nullptr, MAIN);
    cudaStreamWaitEvent(MAIN, s_ev3, 0);
    gat_fused<<<divup((long long)NN * 32, 256), 256>>>(
        (const float4*)C, (const float4*)A, off, cs,
        (const float4*)att, bg, (float4*)D);

    // ---- GCN2 #1 with x0=x2 (128) ----
    prop_launch<32, 1>(D, A, x2, off, cs, cw);
    gemm(A, wt + WOFF_WC1, B, NN, 128, 128, 1, BETA, nullptr, MAIN);

    // ---- x3 = relu(prop(B)@W5 + b5)  (prop commuted to 128-d) ----
    prop_launch<32, 3>(B, A, nullptr, off, cs, cw);
    gemm(A, wt + WOFF_W5, C, NN, 128, 256, 2, 0.0f, b5, MAIN);

    // ---- GCN2 #2 with x0=x1 (256) ----
    prop_launch<64, 1>(C, A, x1, off, cs, cw);
    gemm(A, wt + WOFF_WC2, B, NN, 256, 256, 1, BETA, nullptr, MAIN);

    // ---- out = prop(x3@Wo) + bo ----
    gemm(B, wt + WOFF_WO, A, NN, 256, 128, 0, 0.0f, nullptr, MAIN);
    prop_launch<32, 2>(A, out, bo, off, cs, cw);
}